// round 3
// baseline (speedup 1.0000x reference)
#include <cuda_runtime.h>
#include <math.h>

#define NN 50000
#define EE 800000
#define DIN 128
#define DH 256

// ---------------- scratch (static device globals; no allocations) -----------
__device__ __align__(16) float g_h[NN * DH];
__device__ __align__(16) float g_m[NN * DH];
__device__ __align__(16) float g_res[NN * DH];
__device__ __align__(16) float g_tmp[NN * DH];
__device__ __align__(16) float g_deg[NN];
__device__ __align__(16) float g_isd[NN];   // 1/sqrt(deg)
__device__ __align__(16) float g_id[NN];    // 1/deg
__device__ __align__(16) double g_stats[2 * DH];
__device__ __align__(16) float g_scale[DH];
__device__ __align__(16) float g_shift[DH];

// ---------------- helpers ---------------------------------------------------
__device__ __forceinline__ float gelu_tanh(float x) {
    float x3 = x * x * x;
    return 0.5f * x * (1.0f + tanhf(0.7978845608028654f * (x + 0.044715f * x3)));
}

// ---------------- degree ----------------------------------------------------
__global__ void k_zero_deg() {
    int i = blockIdx.x * blockDim.x + threadIdx.x;
    if (i < NN) g_deg[i] = 0.0f;
}

__global__ void k_deg_count(const int* __restrict__ dst) {
    int e = blockIdx.x * blockDim.x + threadIdx.x;
    if (e < EE) atomicAdd(&g_deg[dst[e]], 1.0f);
}

__global__ void k_deg_final() {
    int i = blockIdx.x * blockDim.x + threadIdx.x;
    if (i < NN) {
        float d = g_deg[i] + 1.0f;  // self loop
        g_isd[i] = rsqrtf(d);
        g_id[i] = 1.0f / d;
    }
}

// ---------------- aggregation ----------------------------------------------
// m[i] = h[i] * inv_deg[i]
template <int D>
__global__ void k_init_scaled(const float* __restrict__ h, float* __restrict__ m) {
    int idx = blockIdx.x * blockDim.x + threadIdx.x;  // float4 index
    if (idx >= NN * (D / 4)) return;
    int row = idx / (D / 4);
    float s = g_id[row];
    float4 v = ((const float4*)h)[idx];
    v.x *= s; v.y *= s; v.z *= s; v.w *= s;
    ((float4*)m)[idx] = v;
}

// m[dst] += h[src] * isd[src]*isd[dst]   (one warp per edge)
template <int D>
__global__ void k_scatter(const float* __restrict__ h, float* __restrict__ m,
                          const int* __restrict__ src,
                          const int* __restrict__ dst) {
    int gw = (blockIdx.x * blockDim.x + threadIdx.x) >> 5;
    int lane = threadIdx.x & 31;
    int nw = (gridDim.x * blockDim.x) >> 5;
    for (int e = gw; e < EE; e += nw) {
        int s = __ldg(&src[e]);
        int d = __ldg(&dst[e]);
        float c = __ldg(&g_isd[s]) * __ldg(&g_isd[d]);
        const float4* hs = (const float4*)(h + (size_t)s * D);
        float4* md = (float4*)(m + (size_t)d * D);
#pragma unroll
        for (int t = 0; t < D / 128; t++) {
            int j = lane + t * 32;
            float4 v = __ldg(&hs[j]);
            v.x *= c; v.y *= c; v.z *= c; v.w *= c;
            asm volatile("red.global.add.v4.f32 [%0], {%1,%2,%3,%4};"
                         :: "l"(md + j), "f"(v.x), "f"(v.y), "f"(v.z), "f"(v.w)
                         : "memory");
        }
    }
}

// ---------------- SGEMM: C[M x 256] = A[M x K] @ B[K x 256] + bias ----------
template <int K, bool GELU>
__global__ void k_sgemm(const float* __restrict__ A, const float* __restrict__ B,
                        const float* __restrict__ bias, float* __restrict__ C, int M) {
    const int BM = 128, BN = 128, BK = 16;
    __shared__ float As[BK][BM];
    __shared__ float Bs[BK][BN];
    int bm = blockIdx.x * BM;
    int bn = blockIdx.y * BN;
    int tid = threadIdx.x;  // 256 threads
    float acc[8][8] = {};
    int tm = (tid / 16) * 8, tn = (tid % 16) * 8;

    for (int k0 = 0; k0 < K; k0 += BK) {
        // A tile: 128x16 = 512 float4, 2 per thread, stored transposed
#pragma unroll
        for (int i = 0; i < 2; i++) {
            int f4 = tid * 2 + i;
            int r = f4 >> 2, c4 = (f4 & 3) * 4;
            int gr = bm + r;
            float4 v = make_float4(0.f, 0.f, 0.f, 0.f);
            if (gr < M) v = *(const float4*)(A + (size_t)gr * K + k0 + c4);
            As[c4 + 0][r] = v.x; As[c4 + 1][r] = v.y;
            As[c4 + 2][r] = v.z; As[c4 + 3][r] = v.w;
        }
        // B tile: 16x128 = 512 float4, 2 per thread
#pragma unroll
        for (int i = 0; i < 2; i++) {
            int f4 = tid * 2 + i;
            int r = f4 >> 5, c4 = (f4 & 31) * 4;
            *(float4*)&Bs[r][c4] = *(const float4*)(B + (size_t)(k0 + r) * DH + bn + c4);
        }
        __syncthreads();
#pragma unroll
        for (int k = 0; k < BK; k++) {
            float a[8], b[8];
#pragma unroll
            for (int i = 0; i < 8; i++) a[i] = As[k][tm + i];
#pragma unroll
            for (int j = 0; j < 8; j++) b[j] = Bs[k][tn + j];
#pragma unroll
            for (int i = 0; i < 8; i++)
#pragma unroll
                for (int j = 0; j < 8; j++) acc[i][j] += a[i] * b[j];
        }
        __syncthreads();
    }
#pragma unroll
    for (int i = 0; i < 8; i++) {
        int gr = bm + tm + i;
        if (gr >= M) continue;
#pragma unroll
        for (int j = 0; j < 8; j++) {
            float v = acc[i][j] + __ldg(&bias[bn + tn + j]);
            if (GELU) v = gelu_tanh(v);
            C[(size_t)gr * DH + bn + tn + j] = v;
        }
    }
}

// ---------------- batchnorm -------------------------------------------------
__global__ void k_zero_stats() {
    int i = blockIdx.x * blockDim.x + threadIdx.x;
    if (i < 2 * DH) g_stats[i] = 0.0;
}

__global__ void k_bn_stats(const float* __restrict__ m) {
    int c = threadIdx.x;  // 256 threads, one per column
    double s = 0.0, ss = 0.0;
    for (int r = blockIdx.x; r < NN; r += gridDim.x) {
        float v = m[(size_t)r * DH + c];
        s += v;
        ss += (double)v * (double)v;
    }
    atomicAdd(&g_stats[c], s);
    atomicAdd(&g_stats[DH + c], ss);
}

__global__ void k_bn_final(const float* __restrict__ gamma, const float* __restrict__ beta) {
    int c = threadIdx.x;
    double mean = g_stats[c] / (double)NN;
    double var = g_stats[DH + c] / (double)NN - mean * mean;
    double sc = (double)gamma[c] / sqrt(var + 1e-5);
    g_scale[c] = (float)sc;
    g_shift[c] = (float)((double)beta[c] - mean * sc);
}

// hout = gelu(m*scale+shift) + res   (res may alias hout)
__global__ void k_bn_apply(const float* __restrict__ m, const float* __restrict__ res,
                           float* __restrict__ hout) {
    int idx = blockIdx.x * blockDim.x + threadIdx.x;  // float4 index
    if (idx >= NN * (DH / 4)) return;
    int c4 = (idx & (DH / 4 - 1)) * 4;
    float4 v = ((const float4*)m)[idx];
    float4 r = ((const float4*)res)[idx];
    float4 o;
    o.x = gelu_tanh(v.x * g_scale[c4 + 0] + g_shift[c4 + 0]) + r.x;
    o.y = gelu_tanh(v.y * g_scale[c4 + 1] + g_shift[c4 + 1]) + r.y;
    o.z = gelu_tanh(v.z * g_scale[c4 + 2] + g_shift[c4 + 2]) + r.z;
    o.w = gelu_tanh(v.w * g_scale[c4 + 3] + g_shift[c4 + 3]) + r.w;
    ((float4*)hout)[idx] = o;
}

// ---------------- head: out[r] = mask[r] ? h[r]·w + b : 0 ------------------
__global__ void k_head(const float* __restrict__ h, const float* __restrict__ w,
                       const float* __restrict__ b, const int* __restrict__ mask,
                       float* __restrict__ out) {
    int gw = (blockIdx.x * blockDim.x + threadIdx.x) >> 5;
    int lane = threadIdx.x & 31;
    if (gw >= NN) return;
    const float4* row = (const float4*)(h + (size_t)gw * DH);
    const float4* w4 = (const float4*)w;
    float s = 0.f;
#pragma unroll
    for (int t = 0; t < 2; t++) {
        int j = lane + t * 32;
        float4 a = row[j];
        float4 ww = __ldg(&w4[j]);
        s += a.x * ww.x + a.y * ww.y + a.z * ww.z + a.w * ww.w;
    }
#pragma unroll
    for (int o = 16; o; o >>= 1) s += __shfl_xor_sync(0xffffffffu, s, o);
    if (lane == 0) out[gw] = (mask[gw] != 0) ? (s + __ldg(&b[0])) : 0.0f;
}

// ---------------- launch -----------------------------------------------------
extern "C" void kernel_launch(void* const* d_in, const int* in_sizes, int n_in,
                              void* d_out, int out_size) {
    const float* x = (const float*)d_in[0];
    const int* ei = (const int*)d_in[1];   // int32 (JAX x64 disabled downcasts int64)
    const int* mask = (const int*)d_in[2]; // bool materialized as int32
    const float* conv_w0 = (const float*)d_in[3];
    const float* conv_b0 = (const float*)d_in[4];
    const float* conv_w1 = (const float*)d_in[5];
    const float* conv_b1 = (const float*)d_in[6];
    const float* conv_w2 = (const float*)d_in[7];
    const float* conv_b2 = (const float*)d_in[8];
    const float* bn_g0 = (const float*)d_in[9];
    const float* bn_b0 = (const float*)d_in[10];
    const float* bn_g1 = (const float*)d_in[11];
    const float* bn_b1 = (const float*)d_in[12];
    const float* bn_g2 = (const float*)d_in[13];
    const float* bn_b2 = (const float*)d_in[14];
    const float* proj_w = (const float*)d_in[15];
    const float* proj_b = (const float*)d_in[16];
    const float* lin_w0 = (const float*)d_in[17];
    const float* lin_b0 = (const float*)d_in[18];
    const float* lin_w1 = (const float*)d_in[19];
    const float* lin_b1 = (const float*)d_in[20];
    const float* head_w = (const float*)d_in[21];
    const float* head_b = (const float*)d_in[22];
    float* out = (float*)d_out;

    const int* src = ei;
    const int* dst = ei + EE;

    float *p_h, *p_m, *p_res, *p_tmp;
    cudaGetSymbolAddress((void**)&p_h, g_h);
    cudaGetSymbolAddress((void**)&p_m, g_m);
    cudaGetSymbolAddress((void**)&p_res, g_res);
    cudaGetSymbolAddress((void**)&p_tmp, g_tmp);

    const int T = 256;
    dim3 gemm_grid((NN + 127) / 128, 2);
    int ew4_128 = NN * (DIN / 4), ew4_256 = NN * (DH / 4);

    // degrees
    k_zero_deg<<<(NN + T - 1) / T, T>>>();
    k_deg_count<<<(EE + T - 1) / T, T>>>(dst);
    k_deg_final<<<(NN + T - 1) / T, T>>>();

    // residual projection: res = x @ proj_w + proj_b
    k_sgemm<DIN, false><<<gemm_grid, T>>>(x, proj_w, proj_b, p_res, NN);

    // ---- GCN layer 0 (input x, D=128) ----
    k_init_scaled<DIN><<<(ew4_128 + T - 1) / T, T>>>(x, p_tmp);
    k_scatter<DIN><<<2048, T>>>(x, p_tmp, src, dst);
    k_sgemm<DIN, false><<<gemm_grid, T>>>(p_tmp, conv_w0, conv_b0, p_m, NN);
    k_zero_stats<<<2, T>>>();
    k_bn_stats<<<512, T>>>(p_m);
    k_bn_final<<<1, T>>>(bn_g0, bn_b0);
    k_bn_apply<<<(ew4_256 + T - 1) / T, T>>>(p_m, p_res, p_h);

    // ---- GCN layer 1 ----
    k_init_scaled<DH><<<(ew4_256 + T - 1) / T, T>>>(p_h, p_tmp);
    k_scatter<DH><<<2048, T>>>(p_h, p_tmp, src, dst);
    k_sgemm<DH, false><<<gemm_grid, T>>>(p_tmp, conv_w1, conv_b1, p_m, NN);
    k_zero_stats<<<2, T>>>();
    k_bn_stats<<<512, T>>>(p_m);
    k_bn_final<<<1, T>>>(bn_g1, bn_b1);
    k_bn_apply<<<(ew4_256 + T - 1) / T, T>>>(p_m, p_h, p_h);

    // ---- GCN layer 2 ----
    k_init_scaled<DH><<<(ew4_256 + T - 1) / T, T>>>(p_h, p_tmp);
    k_scatter<DH><<<2048, T>>>(p_h, p_tmp, src, dst);
    k_sgemm<DH, false><<<gemm_grid, T>>>(p_tmp, conv_w2, conv_b2, p_m, NN);
    k_zero_stats<<<2, T>>>();
    k_bn_stats<<<512, T>>>(p_m);
    k_bn_final<<<1, T>>>(bn_g2, bn_b2);
    k_bn_apply<<<(ew4_256 + T - 1) / T, T>>>(p_m, p_h, p_h);

    // ---- MLP ----
    k_sgemm<DH, true><<<gemm_grid, T>>>(p_h, lin_w0, lin_b0, p_m, NN);
    k_sgemm<DH, true><<<gemm_grid, T>>>(p_m, lin_w1, lin_b1, p_h, NN);

    // ---- head ----
    k_head<<<(NN * 32 + T - 1) / T, T>>>(p_h, head_w, head_b, mask, out);
}

// round 4
// speedup vs baseline: 1.0271x; 1.0271x over previous
#include <cuda_runtime.h>
#include <math.h>

#define NN 50000
#define EE 800000
#define DIN 128
#define DH 256

// ---------------- scratch (static device globals; no allocations) -----------
__device__ __align__(16) float g_h[NN * DH];
__device__ __align__(16) float g_m[NN * DH];
__device__ __align__(16) float g_res[NN * DH];
__device__ __align__(16) float g_tmp[NN * DH];
__device__ __align__(16) float g_deg[NN];
__device__ __align__(16) float g_isd[NN];   // 1/sqrt(deg)
__device__ __align__(16) float g_id[NN];    // 1/deg
__device__ __align__(16) double g_stats[2 * DH];
__device__ __align__(16) float g_scale[DH];
__device__ __align__(16) float g_shift[DH];

// ---------------- helpers ---------------------------------------------------
__device__ __forceinline__ float gelu_tanh(float x) {
    float x3 = x * x * x;
    return 0.5f * x * (1.0f + tanhf(0.7978845608028654f * (x + 0.044715f * x3)));
}

// ---------------- degree ----------------------------------------------------
__global__ void k_zero_deg() {
    int i = blockIdx.x * blockDim.x + threadIdx.x;
    if (i < NN) g_deg[i] = 0.0f;
}

__global__ void k_deg_count(const int* __restrict__ dst) {
    int e = blockIdx.x * blockDim.x + threadIdx.x;
    if (e < EE) atomicAdd(&g_deg[dst[e]], 1.0f);
}

__global__ void k_deg_final() {
    int i = blockIdx.x * blockDim.x + threadIdx.x;
    if (i < NN) {
        float d = g_deg[i] + 1.0f;  // self loop
        g_isd[i] = rsqrtf(d);
        g_id[i] = 1.0f / d;
    }
}

// ---------------- aggregation ----------------------------------------------
// m[i] = h[i] * inv_deg[i]   (only needed for layer 0, from x)
template <int D>
__global__ void k_init_scaled(const float* __restrict__ h, float* __restrict__ m) {
    int idx = blockIdx.x * blockDim.x + threadIdx.x;  // float4 index
    if (idx >= NN * (D / 4)) return;
    int row = idx / (D / 4);
    float s = g_id[row];
    float4 v = ((const float4*)h)[idx];
    v.x *= s; v.y *= s; v.z *= s; v.w *= s;
    ((float4*)m)[idx] = v;
}

// m[dst] += h[src] * isd[src]*isd[dst]   (one warp per edge)
template <int D>
__global__ void k_scatter(const float* __restrict__ h, float* __restrict__ m,
                          const int* __restrict__ src,
                          const int* __restrict__ dst) {
    int gw = (blockIdx.x * blockDim.x + threadIdx.x) >> 5;
    int lane = threadIdx.x & 31;
    int nw = (gridDim.x * blockDim.x) >> 5;
    for (int e = gw; e < EE; e += nw) {
        int s = __ldg(&src[e]);
        int d = __ldg(&dst[e]);
        float c = __ldg(&g_isd[s]) * __ldg(&g_isd[d]);
        const float4* hs = (const float4*)(h + (size_t)s * D);
        float4* md = (float4*)(m + (size_t)d * D);
#pragma unroll
        for (int t = 0; t < D / 128; t++) {
            int j = lane + t * 32;
            float4 v = __ldg(&hs[j]);
            v.x *= c; v.y *= c; v.z *= c; v.w *= c;
            asm volatile("red.global.add.v4.f32 [%0], {%1,%2,%3,%4};"
                         :: "l"(md + j), "f"(v.x), "f"(v.y), "f"(v.z), "f"(v.w)
                         : "memory");
        }
    }
}

// ---------------- SGEMM: C[M x 256] = A[M x K] @ B[K x 256] + bias ----------
// Double-buffered smem, register prefetch of the next global tile.
template <int K, bool GELU>
__global__ void __launch_bounds__(256) k_sgemm(
        const float* __restrict__ A, const float* __restrict__ B,
        const float* __restrict__ bias, float* __restrict__ C, int M) {
    const int BM = 128, BN = 128, BK = 8;
    __shared__ float As[2][BK][BM];
    __shared__ float Bs[2][BK][BN];
    int bm = blockIdx.x * BM;
    int bn = blockIdx.y * BN;
    int tid = threadIdx.x;  // 256 threads
    int tm = (tid / 16) * 8, tn = (tid % 16) * 8;

    // global load mapping (1 float4 each per stage)
    int arow = tid >> 1, acol = (tid & 1) * 4;       // A tile: 128x8
    int brow = tid >> 5, bcol = (tid & 31) * 4;      // B tile: 8x128
    const float* Aptr = A + (size_t)(bm + arow) * K + acol;
    const float* Bptr = B + (size_t)brow * DH + bn + bcol;
    bool aok = (bm + arow) < M;

    float acc[8][8] = {};

    // stage 0
    float4 av = aok ? *(const float4*)Aptr : make_float4(0.f, 0.f, 0.f, 0.f);
    float4 bv = *(const float4*)Bptr;
    As[0][acol + 0][arow] = av.x; As[0][acol + 1][arow] = av.y;
    As[0][acol + 2][arow] = av.z; As[0][acol + 3][arow] = av.w;
    *(float4*)&Bs[0][brow][bcol] = bv;
    __syncthreads();

    int buf = 0;
#pragma unroll
    for (int k0 = BK; k0 <= K; k0 += BK) {
        bool more = k0 < K;
        float4 av2, bv2;
        if (more) {  // issue next-tile loads early; consumed after compute
            av2 = aok ? *(const float4*)(Aptr + k0) : make_float4(0.f, 0.f, 0.f, 0.f);
            bv2 = *(const float4*)(Bptr + (size_t)k0 * DH);
        }
#pragma unroll
        for (int kk = 0; kk < BK; kk++) {
            float a[8], b[8];
#pragma unroll
            for (int i = 0; i < 8; i++) a[i] = As[buf][kk][tm + i];
#pragma unroll
            for (int j = 0; j < 8; j++) b[j] = Bs[buf][kk][tn + j];
#pragma unroll
            for (int i = 0; i < 8; i++)
#pragma unroll
                for (int j = 0; j < 8; j++) acc[i][j] += a[i] * b[j];
        }
        if (more) {
            int nb = buf ^ 1;
            As[nb][acol + 0][arow] = av2.x; As[nb][acol + 1][arow] = av2.y;
            As[nb][acol + 2][arow] = av2.z; As[nb][acol + 3][arow] = av2.w;
            *(float4*)&Bs[nb][brow][bcol] = bv2;
            __syncthreads();
            buf = nb;
        }
    }

#pragma unroll
    for (int i = 0; i < 8; i++) {
        int gr = bm + tm + i;
        if (gr >= M) continue;
#pragma unroll
        for (int j = 0; j < 8; j += 4) {
            float4 o;
            o.x = acc[i][j + 0] + __ldg(&bias[bn + tn + j + 0]);
            o.y = acc[i][j + 1] + __ldg(&bias[bn + tn + j + 1]);
            o.z = acc[i][j + 2] + __ldg(&bias[bn + tn + j + 2]);
            o.w = acc[i][j + 3] + __ldg(&bias[bn + tn + j + 3]);
            if (GELU) {
                o.x = gelu_tanh(o.x); o.y = gelu_tanh(o.y);
                o.z = gelu_tanh(o.z); o.w = gelu_tanh(o.w);
            }
            *(float4*)(C + (size_t)gr * DH + bn + tn + j) = o;
        }
    }
}

// ---------------- batchnorm -------------------------------------------------
__global__ void k_zero_stats() {
    int i = blockIdx.x * blockDim.x + threadIdx.x;
    if (i < 2 * DH) g_stats[i] = 0.0;
}

__global__ void k_bn_stats(const float* __restrict__ m) {
    int c = threadIdx.x;  // 256 threads, one per column
    double s = 0.0, ss = 0.0;
    for (int r = blockIdx.x; r < NN; r += gridDim.x) {
        float v = m[(size_t)r * DH + c];
        s += v;
        ss += (double)v * (double)v;
    }
    atomicAdd(&g_stats[c], s);
    atomicAdd(&g_stats[DH + c], ss);
}

__global__ void k_bn_final(const float* __restrict__ gamma, const float* __restrict__ beta) {
    int c = threadIdx.x;
    double mean = g_stats[c] / (double)NN;
    double var = g_stats[DH + c] / (double)NN - mean * mean;
    double sc = (double)gamma[c] / sqrt(var + 1e-5);
    g_scale[c] = (float)sc;
    g_shift[c] = (float)((double)beta[c] - mean * sc);
}

// hout = gelu(m*scale+shift) + res; optionally also tmp = hout * inv_deg
template <bool SCALED_OUT>
__global__ void k_bn_apply(const float* __restrict__ m, const float* __restrict__ res,
                           float* __restrict__ hout, float* __restrict__ tmp) {
    int idx = blockIdx.x * blockDim.x + threadIdx.x;  // float4 index
    if (idx >= NN * (DH / 4)) return;
    int c4 = (idx & (DH / 4 - 1)) * 4;
    float4 v = ((const float4*)m)[idx];
    float4 r = ((const float4*)res)[idx];
    float4 o;
    o.x = gelu_tanh(v.x * g_scale[c4 + 0] + g_shift[c4 + 0]) + r.x;
    o.y = gelu_tanh(v.y * g_scale[c4 + 1] + g_shift[c4 + 1]) + r.y;
    o.z = gelu_tanh(v.z * g_scale[c4 + 2] + g_shift[c4 + 2]) + r.z;
    o.w = gelu_tanh(v.w * g_scale[c4 + 3] + g_shift[c4 + 3]) + r.w;
    ((float4*)hout)[idx] = o;
    if (SCALED_OUT) {
        float s = g_id[idx >> 6];  // DH/4 = 64 float4 per row
        float4 t = make_float4(o.x * s, o.y * s, o.z * s, o.w * s);
        ((float4*)tmp)[idx] = t;
    }
}

// ---------------- head: out[r] = mask[r] ? h[r]·w + b : 0 ------------------
__global__ void k_head(const float* __restrict__ h, const float* __restrict__ w,
                       const float* __restrict__ b, const int* __restrict__ mask,
                       float* __restrict__ out) {
    int gw = (blockIdx.x * blockDim.x + threadIdx.x) >> 5;
    int lane = threadIdx.x & 31;
    if (gw >= NN) return;
    const float4* row = (const float4*)(h + (size_t)gw * DH);
    const float4* w4 = (const float4*)w;
    float s = 0.f;
#pragma unroll
    for (int t = 0; t < 2; t++) {
        int j = lane + t * 32;
        float4 a = row[j];
        float4 ww = __ldg(&w4[j]);
        s += a.x * ww.x + a.y * ww.y + a.z * ww.z + a.w * ww.w;
    }
#pragma unroll
    for (int o = 16; o; o >>= 1) s += __shfl_xor_sync(0xffffffffu, s, o);
    if (lane == 0) out[gw] = (mask[gw] != 0) ? (s + __ldg(&b[0])) : 0.0f;
}

// ---------------- launch -----------------------------------------------------
extern "C" void kernel_launch(void* const* d_in, const int* in_sizes, int n_in,
                              void* d_out, int out_size) {
    const float* x = (const float*)d_in[0];
    const int* ei = (const int*)d_in[1];   // int32 (JAX x64 disabled downcasts int64)
    const int* mask = (const int*)d_in[2]; // bool materialized as int32
    const float* conv_w0 = (const float*)d_in[3];
    const float* conv_b0 = (const float*)d_in[4];
    const float* conv_w1 = (const float*)d_in[5];
    const float* conv_b1 = (const float*)d_in[6];
    const float* conv_w2 = (const float*)d_in[7];
    const float* conv_b2 = (const float*)d_in[8];
    const float* bn_g0 = (const float*)d_in[9];
    const float* bn_b0 = (const float*)d_in[10];
    const float* bn_g1 = (const float*)d_in[11];
    const float* bn_b1 = (const float*)d_in[12];
    const float* bn_g2 = (const float*)d_in[13];
    const float* bn_b2 = (const float*)d_in[14];
    const float* proj_w = (const float*)d_in[15];
    const float* proj_b = (const float*)d_in[16];
    const float* lin_w0 = (const float*)d_in[17];
    const float* lin_b0 = (const float*)d_in[18];
    const float* lin_w1 = (const float*)d_in[19];
    const float* lin_b1 = (const float*)d_in[20];
    const float* head_w = (const float*)d_in[21];
    const float* head_b = (const float*)d_in[22];
    float* out = (float*)d_out;

    const int* src = ei;
    const int* dst = ei + EE;

    float *p_h, *p_m, *p_res, *p_tmp;
    cudaGetSymbolAddress((void**)&p_h, g_h);
    cudaGetSymbolAddress((void**)&p_m, g_m);
    cudaGetSymbolAddress((void**)&p_res, g_res);
    cudaGetSymbolAddress((void**)&p_tmp, g_tmp);

    const int T = 256;
    dim3 gemm_grid((NN + 127) / 128, 2);
    int ew4_128 = NN * (DIN / 4), ew4_256 = NN * (DH / 4);

    // degrees
    k_zero_deg<<<(NN + T - 1) / T, T>>>();
    k_deg_count<<<(EE + T - 1) / T, T>>>(dst);
    k_deg_final<<<(NN + T - 1) / T, T>>>();

    // residual projection: res = x @ proj_w + proj_b
    k_sgemm<DIN, false><<<gemm_grid, T>>>(x, proj_w, proj_b, p_res, NN);

    // ---- GCN layer 0 (input x, D=128) ----
    k_init_scaled<DIN><<<(ew4_128 + T - 1) / T, T>>>(x, p_tmp);
    k_scatter<DIN><<<2048, T>>>(x, p_tmp, src, dst);
    k_sgemm<DIN, false><<<gemm_grid, T>>>(p_tmp, conv_w0, conv_b0, p_m, NN);
    k_zero_stats<<<2, T>>>();
    k_bn_stats<<<512, T>>>(p_m);
    k_bn_final<<<1, T>>>(bn_g0, bn_b0);
    k_bn_apply<true><<<(ew4_256 + T - 1) / T, T>>>(p_m, p_res, p_h, p_tmp);

    // ---- GCN layer 1 ----
    k_scatter<DH><<<2048, T>>>(p_h, p_tmp, src, dst);
    k_sgemm<DH, false><<<gemm_grid, T>>>(p_tmp, conv_w1, conv_b1, p_m, NN);
    k_zero_stats<<<2, T>>>();
    k_bn_stats<<<512, T>>>(p_m);
    k_bn_final<<<1, T>>>(bn_g1, bn_b1);
    k_bn_apply<true><<<(ew4_256 + T - 1) / T, T>>>(p_m, p_h, p_h, p_tmp);

    // ---- GCN layer 2 ----
    k_scatter<DH><<<2048, T>>>(p_h, p_tmp, src, dst);
    k_sgemm<DH, false><<<gemm_grid, T>>>(p_tmp, conv_w2, conv_b2, p_m, NN);
    k_zero_stats<<<2, T>>>();
    k_bn_stats<<<512, T>>>(p_m);
    k_bn_final<<<1, T>>>(bn_g2, bn_b2);
    k_bn_apply<false><<<(ew4_256 + T - 1) / T, T>>>(p_m, p_h, p_h, p_tmp);

    // ---- MLP ----
    k_sgemm<DH, true><<<gemm_grid, T>>>(p_h, lin_w0, lin_b0, p_m, NN);
    k_sgemm<DH, true><<<gemm_grid, T>>>(p_m, lin_w1, lin_b1, p_h, NN);

    // ---- head ----
    k_head<<<(NN * 32 + T - 1) / T, T>>>(p_h, head_w, head_b, mask, out);
}

// round 5
// speedup vs baseline: 1.2425x; 1.2098x over previous
#include <cuda_runtime.h>
#include <math.h>

#define NN 50000
#define EE 800000
#define DIN 128
#define DH 256

// ---------------- scratch (static device globals; no allocations) -----------
__device__ __align__(16) float g_h[NN * DH];
__device__ __align__(16) float g_m[NN * DH];
__device__ __align__(16) float g_res[NN * DH];
__device__ __align__(16) float g_tmp[NN * DH];
__device__ __align__(16) float g_deg[NN];
__device__ __align__(16) float g_isd[NN];   // 1/sqrt(deg)
__device__ __align__(16) float g_id[NN];    // 1/deg
__device__ __align__(16) double g_stats[2 * DH];
__device__ __align__(16) float g_scale[DH];
__device__ __align__(16) float g_shift[DH];

// ---------------- helpers ---------------------------------------------------
__device__ __forceinline__ float gelu_tanh(float x) {
    float x3 = x * x * x;
    return 0.5f * x * (1.0f + tanhf(0.7978845608028654f * (x + 0.044715f * x3)));
}

__device__ __forceinline__ unsigned cvt_tf32(float f) {
    unsigned u;
    asm("cvt.rna.tf32.f32 %0, %1;" : "=r"(u) : "f"(f));
    return u;
}

// split f into hi (tf32) + lo (tf32 of remainder)
__device__ __forceinline__ void tf32_split(float f, unsigned& hi, unsigned& lo) {
    hi = cvt_tf32(f);
    lo = cvt_tf32(f - __uint_as_float(hi));
}

__device__ __forceinline__ void mma_tf32(float& c0, float& c1, float& c2, float& c3,
                                         unsigned a0, unsigned a1, unsigned a2, unsigned a3,
                                         unsigned b0, unsigned b1) {
    asm volatile("mma.sync.aligned.m16n8k8.row.col.f32.tf32.tf32.f32 "
                 "{%0,%1,%2,%3},{%4,%5,%6,%7},{%8,%9},{%0,%1,%2,%3};"
                 : "+f"(c0), "+f"(c1), "+f"(c2), "+f"(c3)
                 : "r"(a0), "r"(a1), "r"(a2), "r"(a3), "r"(b0), "r"(b1));
}

// ---------------- degree ----------------------------------------------------
__global__ void k_zero_deg() {
    int i = blockIdx.x * blockDim.x + threadIdx.x;
    if (i < NN) g_deg[i] = 0.0f;
}

__global__ void k_deg_count(const int* __restrict__ dst) {
    int e = blockIdx.x * blockDim.x + threadIdx.x;
    if (e < EE) atomicAdd(&g_deg[dst[e]], 1.0f);
}

__global__ void k_deg_final() {
    int i = blockIdx.x * blockDim.x + threadIdx.x;
    if (i < NN) {
        float d = g_deg[i] + 1.0f;  // self loop
        g_isd[i] = rsqrtf(d);
        g_id[i] = 1.0f / d;
    }
}

// ---------------- aggregation ----------------------------------------------
template <int D>
__global__ void k_init_scaled(const float* __restrict__ h, float* __restrict__ m) {
    int idx = blockIdx.x * blockDim.x + threadIdx.x;  // float4 index
    if (idx >= NN * (D / 4)) return;
    int row = idx / (D / 4);
    float s = g_id[row];
    float4 v = ((const float4*)h)[idx];
    v.x *= s; v.y *= s; v.z *= s; v.w *= s;
    ((float4*)m)[idx] = v;
}

// m[dst] += h[src] * isd[src]*isd[dst]   (one warp per edge)
template <int D>
__global__ void k_scatter(const float* __restrict__ h, float* __restrict__ m,
                          const int* __restrict__ src,
                          const int* __restrict__ dst) {
    int gw = (blockIdx.x * blockDim.x + threadIdx.x) >> 5;
    int lane = threadIdx.x & 31;
    int nw = (gridDim.x * blockDim.x) >> 5;
    for (int e = gw; e < EE; e += nw) {
        int s = __ldg(&src[e]);
        int d = __ldg(&dst[e]);
        float c = __ldg(&g_isd[s]) * __ldg(&g_isd[d]);
        const float4* hs = (const float4*)(h + (size_t)s * D);
        float4* md = (float4*)(m + (size_t)d * D);
#pragma unroll
        for (int t = 0; t < D / 128; t++) {
            int j = lane + t * 32;
            float4 v = __ldg(&hs[j]);
            v.x *= c; v.y *= c; v.z *= c; v.w *= c;
            asm volatile("red.global.add.v4.f32 [%0], {%1,%2,%3,%4};"
                         :: "l"(md + j), "f"(v.x), "f"(v.y), "f"(v.z), "f"(v.w)
                         : "memory");
        }
    }
}

// ---------------- tensor-core GEMM (3xTF32): C[MxDH] = A[MxK] @ B[KxDH] -----
// block 128(M) x 64(N), BK=16, 256 threads = 8 warps, warp tile 32x32
template <int K, bool GELU>
__global__ void __launch_bounds__(256) k_tgemm(
        const float* __restrict__ A, const float* __restrict__ B,
        const float* __restrict__ bias, float* __restrict__ C, int M) {
    const int BM = 128, BN = 64, BK = 16;
    const int AS = 18;  // padded row stride for A tile (floats)
    const int BS = 68;  // padded row stride for B tile (floats)
    __shared__ float As[2][BM * AS];
    __shared__ float Bs[2][BK * BS];

    int bm = blockIdx.x * BM;
    int bn = blockIdx.y * BN;
    int tid = threadIdx.x;
    int wid = tid >> 5, lane = tid & 31;
    int g = lane >> 2, t = lane & 3;
    int warp_m = (wid & 3) * 32;   // 0..96
    int warp_n = (wid >> 2) * 32;  // 0 or 32

    // global load mapping
    int arow = tid >> 1;                      // A tile: 128 rows x 16 (2 f4/thread)
    int ac4 = (tid & 1) * 8;                  // this thread covers cols [ac4, ac4+8)
    int brow = tid >> 4, bc4 = (tid & 15) * 4;  // B tile: 16 x 64, 1 f4/thread
    const float* Aptr = A + (size_t)(bm + arow) * K + ac4;
    const float* Bptr = B + (size_t)brow * DH + bn + bc4;
    bool aok = (bm + arow) < M;

    float acc[2][4][4];  // [m frag][n frag][c0..c3]
#pragma unroll
    for (int m = 0; m < 2; m++)
#pragma unroll
        for (int n = 0; n < 4; n++)
#pragma unroll
            for (int c = 0; c < 4; c++) acc[m][n][c] = 0.f;

    // ---- stage 0 ----
    {
        float4 a0 = make_float4(0.f, 0.f, 0.f, 0.f), a1 = a0;
        if (aok) { a0 = *(const float4*)Aptr; a1 = *(const float4*)(Aptr + 4); }
        float4 bv = *(const float4*)Bptr;
        float* as = &As[0][arow * AS + ac4];
        as[0] = a0.x; as[1] = a0.y; as[2] = a0.z; as[3] = a0.w;
        as[4] = a1.x; as[5] = a1.y; as[6] = a1.z; as[7] = a1.w;
        float* bs = &Bs[0][brow * BS + bc4];
        bs[0] = bv.x; bs[1] = bv.y; bs[2] = bv.z; bs[3] = bv.w;
    }
    __syncthreads();

    int buf = 0;
#pragma unroll
    for (int k0 = BK; k0 <= K; k0 += BK) {
        bool more = k0 < K;
        float4 pa0, pa1, pbv;
        if (more) {
            pa0 = make_float4(0.f, 0.f, 0.f, 0.f); pa1 = pa0;
            if (aok) { pa0 = *(const float4*)(Aptr + k0); pa1 = *(const float4*)(Aptr + k0 + 4); }
            pbv = *(const float4*)(Bptr + (size_t)k0 * DH);
        }

        const float* as = &As[buf][0];
        const float* bs = &Bs[buf][0];
#pragma unroll
        for (int ks = 0; ks < BK; ks += 8) {
            unsigned aHi[2][4], aLo[2][4], bHi[4][2], bLo[4][2];
#pragma unroll
            for (int m = 0; m < 2; m++) {
                int r0 = warp_m + m * 16;
                tf32_split(as[(r0 + g) * AS + ks + t],     aHi[m][0], aLo[m][0]);
                tf32_split(as[(r0 + g + 8) * AS + ks + t], aHi[m][1], aLo[m][1]);
                tf32_split(as[(r0 + g) * AS + ks + t + 4],     aHi[m][2], aLo[m][2]);
                tf32_split(as[(r0 + g + 8) * AS + ks + t + 4], aHi[m][3], aLo[m][3]);
            }
#pragma unroll
            for (int n = 0; n < 4; n++) {
                int n0 = warp_n + n * 8 + g;
                tf32_split(bs[(ks + t) * BS + n0],     bHi[n][0], bLo[n][0]);
                tf32_split(bs[(ks + t + 4) * BS + n0], bHi[n][1], bLo[n][1]);
            }
#pragma unroll
            for (int m = 0; m < 2; m++)
#pragma unroll
                for (int n = 0; n < 4; n++) {
                    float* c = acc[m][n];
                    mma_tf32(c[0], c[1], c[2], c[3],
                             aLo[m][0], aLo[m][1], aLo[m][2], aLo[m][3],
                             bHi[n][0], bHi[n][1]);
                    mma_tf32(c[0], c[1], c[2], c[3],
                             aHi[m][0], aHi[m][1], aHi[m][2], aHi[m][3],
                             bLo[n][0], bLo[n][1]);
                    mma_tf32(c[0], c[1], c[2], c[3],
                             aHi[m][0], aHi[m][1], aHi[m][2], aHi[m][3],
                             bHi[n][0], bHi[n][1]);
                }
        }

        if (more) {
            int nb = buf ^ 1;
            float* asn = &As[nb][arow * AS + ac4];
            asn[0] = pa0.x; asn[1] = pa0.y; asn[2] = pa0.z; asn[3] = pa0.w;
            asn[4] = pa1.x; asn[5] = pa1.y; asn[6] = pa1.z; asn[7] = pa1.w;
            float* bsn = &Bs[nb][brow * BS + bc4];
            bsn[0] = pbv.x; bsn[1] = pbv.y; bsn[2] = pbv.z; bsn[3] = pbv.w;
            __syncthreads();
            buf = nb;
        }
    }

    // ---- epilogue ----
#pragma unroll
    for (int m = 0; m < 2; m++) {
        int row0 = bm + warp_m + m * 16;
#pragma unroll
        for (int n = 0; n < 4; n++) {
            int col = bn + warp_n + n * 8 + t * 2;
            float b0 = __ldg(&bias[col]), b1 = __ldg(&bias[col + 1]);
            int r = row0 + g;
            if (r < M) {
                float2 o = make_float2(acc[m][n][0] + b0, acc[m][n][1] + b1);
                if (GELU) { o.x = gelu_tanh(o.x); o.y = gelu_tanh(o.y); }
                *(float2*)(C + (size_t)r * DH + col) = o;
            }
            int r2 = row0 + g + 8;
            if (r2 < M) {
                float2 o = make_float2(acc[m][n][2] + b0, acc[m][n][3] + b1);
                if (GELU) { o.x = gelu_tanh(o.x); o.y = gelu_tanh(o.y); }
                *(float2*)(C + (size_t)r2 * DH + col) = o;
            }
        }
    }
}

// ---------------- batchnorm -------------------------------------------------
__global__ void k_zero_stats() {
    int i = blockIdx.x * blockDim.x + threadIdx.x;
    if (i < 2 * DH) g_stats[i] = 0.0;
}

__global__ void k_bn_stats(const float* __restrict__ m) {
    int c = threadIdx.x;  // 256 threads, one per column
    double s = 0.0, ss = 0.0;
    for (int r = blockIdx.x; r < NN; r += gridDim.x) {
        float v = m[(size_t)r * DH + c];
        s += v;
        ss += (double)v * (double)v;
    }
    atomicAdd(&g_stats[c], s);
    atomicAdd(&g_stats[DH + c], ss);
}

__global__ void k_bn_final(const float* __restrict__ gamma, const float* __restrict__ beta) {
    int c = threadIdx.x;
    double mean = g_stats[c] / (double)NN;
    double var = g_stats[DH + c] / (double)NN - mean * mean;
    double sc = (double)gamma[c] / sqrt(var + 1e-5);
    g_scale[c] = (float)sc;
    g_shift[c] = (float)((double)beta[c] - mean * sc);
}

// hout = gelu(m*scale+shift) + res; optionally also tmp = hout * inv_deg
template <bool SCALED_OUT>
__global__ void k_bn_apply(const float* __restrict__ m, const float* __restrict__ res,
                           float* __restrict__ hout, float* __restrict__ tmp) {
    int idx = blockIdx.x * blockDim.x + threadIdx.x;  // float4 index
    if (idx >= NN * (DH / 4)) return;
    int c4 = (idx & (DH / 4 - 1)) * 4;
    float4 v = ((const float4*)m)[idx];
    float4 r = ((const float4*)res)[idx];
    float4 o;
    o.x = gelu_tanh(v.x * g_scale[c4 + 0] + g_shift[c4 + 0]) + r.x;
    o.y = gelu_tanh(v.y * g_scale[c4 + 1] + g_shift[c4 + 1]) + r.y;
    o.z = gelu_tanh(v.z * g_scale[c4 + 2] + g_shift[c4 + 2]) + r.z;
    o.w = gelu_tanh(v.w * g_scale[c4 + 3] + g_shift[c4 + 3]) + r.w;
    ((float4*)hout)[idx] = o;
    if (SCALED_OUT) {
        float s = g_id[idx >> 6];  // DH/4 = 64 float4 per row
        float4 t = make_float4(o.x * s, o.y * s, o.z * s, o.w * s);
        ((float4*)tmp)[idx] = t;
    }
}

// ---------------- head: out[r] = mask[r] ? h[r]·w + b : 0 ------------------
__global__ void k_head(const float* __restrict__ h, const float* __restrict__ w,
                       const float* __restrict__ b, const int* __restrict__ mask,
                       float* __restrict__ out) {
    int gw = (blockIdx.x * blockDim.x + threadIdx.x) >> 5;
    int lane = threadIdx.x & 31;
    if (gw >= NN) return;
    const float4* row = (const float4*)(h + (size_t)gw * DH);
    const float4* w4 = (const float4*)w;
    float s = 0.f;
#pragma unroll
    for (int t = 0; t < 2; t++) {
        int j = lane + t * 32;
        float4 a = row[j];
        float4 ww = __ldg(&w4[j]);
        s += a.x * ww.x + a.y * ww.y + a.z * ww.z + a.w * ww.w;
    }
#pragma unroll
    for (int o = 16; o; o >>= 1) s += __shfl_xor_sync(0xffffffffu, s, o);
    if (lane == 0) out[gw] = (mask[gw] != 0) ? (s + __ldg(&b[0])) : 0.0f;
}

// ---------------- launch -----------------------------------------------------
extern "C" void kernel_launch(void* const* d_in, const int* in_sizes, int n_in,
                              void* d_out, int out_size) {
    const float* x = (const float*)d_in[0];
    const int* ei = (const int*)d_in[1];   // int32 (JAX x64 disabled downcasts int64)
    const int* mask = (const int*)d_in[2]; // bool materialized as int32
    const float* conv_w0 = (const float*)d_in[3];
    const float* conv_b0 = (const float*)d_in[4];
    const float* conv_w1 = (const float*)d_in[5];
    const float* conv_b1 = (const float*)d_in[6];
    const float* conv_w2 = (const float*)d_in[7];
    const float* conv_b2 = (const float*)d_in[8];
    const float* bn_g0 = (const float*)d_in[9];
    const float* bn_b0 = (const float*)d_in[10];
    const float* bn_g1 = (const float*)d_in[11];
    const float* bn_b1 = (const float*)d_in[12];
    const float* bn_g2 = (const float*)d_in[13];
    const float* bn_b2 = (const float*)d_in[14];
    const float* proj_w = (const float*)d_in[15];
    const float* proj_b = (const float*)d_in[16];
    const float* lin_w0 = (const float*)d_in[17];
    const float* lin_b0 = (const float*)d_in[18];
    const float* lin_w1 = (const float*)d_in[19];
    const float* lin_b1 = (const float*)d_in[20];
    const float* head_w = (const float*)d_in[21];
    const float* head_b = (const float*)d_in[22];
    float* out = (float*)d_out;

    const int* src = ei;
    const int* dst = ei + EE;

    float *p_h, *p_m, *p_res, *p_tmp;
    cudaGetSymbolAddress((void**)&p_h, g_h);
    cudaGetSymbolAddress((void**)&p_m, g_m);
    cudaGetSymbolAddress((void**)&p_res, g_res);
    cudaGetSymbolAddress((void**)&p_tmp, g_tmp);

    const int T = 256;
    dim3 tg_grid((NN + 127) / 128, DH / 64);  // 391 x 4
    int ew4_128 = NN * (DIN / 4), ew4_256 = NN * (DH / 4);

    // degrees
    k_zero_deg<<<(NN + T - 1) / T, T>>>();
    k_deg_count<<<(EE + T - 1) / T, T>>>(dst);
    k_deg_final<<<(NN + T - 1) / T, T>>>();

    // residual projection: res = x @ proj_w + proj_b
    k_tgemm<DIN, false><<<tg_grid, T>>>(x, proj_w, proj_b, p_res, NN);

    // ---- GCN layer 0 (input x, D=128) ----
    k_init_scaled<DIN><<<(ew4_128 + T - 1) / T, T>>>(x, p_tmp);
    k_scatter<DIN><<<2048, T>>>(x, p_tmp, src, dst);
    k_tgemm<DIN, false><<<tg_grid, T>>>(p_tmp, conv_w0, conv_b0, p_m, NN);
    k_zero_stats<<<2, T>>>();
    k_bn_stats<<<512, T>>>(p_m);
    k_bn_final<<<1, T>>>(bn_g0, bn_b0);
    k_bn_apply<true><<<(ew4_256 + T - 1) / T, T>>>(p_m, p_res, p_h, p_tmp);

    // ---- GCN layer 1 ----
    k_scatter<DH><<<2048, T>>>(p_h, p_tmp, src, dst);
    k_tgemm<DH, false><<<tg_grid, T>>>(p_tmp, conv_w1, conv_b1, p_m, NN);
    k_zero_stats<<<2, T>>>();
    k_bn_stats<<<512, T>>>(p_m);
    k_bn_final<<<1, T>>>(bn_g1, bn_b1);
    k_bn_apply<true><<<(ew4_256 + T - 1) / T, T>>>(p_m, p_h, p_h, p_tmp);

    // ---- GCN layer 2 ----
    k_scatter<DH><<<2048, T>>>(p_h, p_tmp, src, dst);
    k_tgemm<DH, false><<<tg_grid, T>>>(p_tmp, conv_w2, conv_b2, p_m, NN);
    k_zero_stats<<<2, T>>>();
    k_bn_stats<<<512, T>>>(p_m);
    k_bn_final<<<1, T>>>(bn_g2, bn_b2);
    k_bn_apply<false><<<(ew4_256 + T - 1) / T, T>>>(p_m, p_h, p_h, p_tmp);

    // ---- MLP ----
    k_tgemm<DH, true><<<tg_grid, T>>>(p_h, lin_w0, lin_b0, p_m, NN);
    k_tgemm<DH, true><<<tg_grid, T>>>(p_m, lin_w1, lin_b1, p_h, NN);

    // ---- head ----
    k_head<<<(NN * 32 + T - 1) / T, T>>>(p_h, head_w, head_b, mask, out);
}

// round 6
// speedup vs baseline: 1.2787x; 1.0291x over previous
#include <cuda_runtime.h>
#include <math.h>

#define NN 50000
#define EE 800000
#define DIN 128
#define DH 256

// ---------------- scratch (static device globals; no allocations) -----------
__device__ __align__(16) float g_h[NN * DH];
__device__ __align__(16) float g_m[NN * DH];
__device__ __align__(16) float g_res[NN * DH];
__device__ __align__(16) float g_tmp[NN * DH];
__device__ __align__(16) int   g_cnt[NN];
__device__ __align__(16) int   g_off[NN + 1];
__device__ __align__(16) int   g_cursor[NN];
__device__ __align__(16) int   g_csr[EE];
__device__ __align__(16) float g_isd[NN];   // 1/sqrt(deg)
__device__ __align__(16) float g_id[NN];    // 1/deg
__device__ __align__(16) double g_stats[2 * DH];
__device__ __align__(16) float g_scale[DH];
__device__ __align__(16) float g_shift[DH];

// ---------------- helpers ---------------------------------------------------
__device__ __forceinline__ float gelu_tanh(float x) {
    float x3 = x * x * x;
    return 0.5f * x * (1.0f + tanhf(0.7978845608028654f * (x + 0.044715f * x3)));
}

__device__ __forceinline__ float cvt_tf32f(float f) {
    unsigned u;
    asm("cvt.rna.tf32.f32 %0, %1;" : "=r"(u) : "f"(f));
    return __uint_as_float(u);
}

// split f into (hi, lo) tf32-representable floats
__device__ __forceinline__ float2 tf32_split2(float f) {
    float hi = cvt_tf32f(f);
    float lo = cvt_tf32f(f - hi);
    return make_float2(hi, lo);
}

__device__ __forceinline__ void mma_tf32(float& c0, float& c1, float& c2, float& c3,
                                         float a0, float a1, float a2, float a3,
                                         float b0, float b1) {
    asm volatile("mma.sync.aligned.m16n8k8.row.col.f32.tf32.tf32.f32 "
                 "{%0,%1,%2,%3},{%4,%5,%6,%7},{%8,%9},{%0,%1,%2,%3};"
                 : "+f"(c0), "+f"(c1), "+f"(c2), "+f"(c3)
                 : "r"(__float_as_uint(a0)), "r"(__float_as_uint(a1)),
                   "r"(__float_as_uint(a2)), "r"(__float_as_uint(a3)),
                   "r"(__float_as_uint(b0)), "r"(__float_as_uint(b1)));
}

// ---------------- degree + CSR ----------------------------------------------
__global__ void k_zero_cnt() {
    int i = blockIdx.x * blockDim.x + threadIdx.x;
    if (i < NN) g_cnt[i] = 0;
}

__global__ void k_deg_count(const int* __restrict__ dst) {
    int e = blockIdx.x * blockDim.x + threadIdx.x;
    if (e < EE) atomicAdd(&g_cnt[dst[e]], 1);
}

__global__ void k_deg_final() {
    int i = blockIdx.x * blockDim.x + threadIdx.x;
    if (i < NN) {
        float d = (float)g_cnt[i] + 1.0f;  // self loop
        g_isd[i] = rsqrtf(d);
        g_id[i] = 1.0f / d;
    }
}

// single-block inclusive scan over g_cnt -> g_off (exclusive in cursor)
__global__ void k_scan() {
    __shared__ int sm[1024];
    __shared__ int carry;
    if (threadIdx.x == 0) carry = 0;
    __syncthreads();
    for (int base = 0; base < NN; base += 1024) {
        int i = base + threadIdx.x;
        int v = (i < NN) ? g_cnt[i] : 0;
        sm[threadIdx.x] = v;
        __syncthreads();
#pragma unroll
        for (int off = 1; off < 1024; off <<= 1) {
            int t = (threadIdx.x >= off) ? sm[threadIdx.x - off] : 0;
            __syncthreads();
            sm[threadIdx.x] += t;
            __syncthreads();
        }
        int incl = sm[threadIdx.x] + carry;
        if (i < NN) { g_off[i + 1] = incl; g_cursor[i] = incl - v; }
        __syncthreads();
        if (threadIdx.x == 1023) carry = incl;
        __syncthreads();
    }
    if (threadIdx.x == 0) g_off[0] = 0;
}

__global__ void k_csr_fill(const int* __restrict__ src, const int* __restrict__ dst) {
    int e = blockIdx.x * blockDim.x + threadIdx.x;
    if (e < EE) {
        int p = atomicAdd(&g_cursor[dst[e]], 1);
        g_csr[p] = src[e];
    }
}

// ---------------- aggregation: warp-per-node CSR gather ---------------------
// m[i] = id_i * h[i] + isd_i * sum_{s->i} isd_s * h[s]
template <int D>
__global__ void k_gather(const float* __restrict__ h, float* __restrict__ m) {
    int w = (blockIdx.x * blockDim.x + threadIdx.x) >> 5;
    int lane = threadIdx.x & 31;
    if (w >= NN) return;
    const int NF = D / 128;  // float4 per lane
    const float4* hn = (const float4*)(h + (size_t)w * D);
    float idg = g_id[w], isdd = g_isd[w];
    float4 acc[NF];
#pragma unroll
    for (int t = 0; t < NF; t++) {
        float4 v = hn[lane + 32 * t];
        acc[t] = make_float4(v.x * idg, v.y * idg, v.z * idg, v.w * idg);
    }
    int e0 = g_off[w], e1 = g_off[w + 1];
    for (int e = e0; e < e1; e++) {
        int s = __ldg(&g_csr[e]);
        float c = isdd * __ldg(&g_isd[s]);
        const float4* hs = (const float4*)(h + (size_t)s * D);
#pragma unroll
        for (int t = 0; t < NF; t++) {
            float4 v = __ldg(&hs[lane + 32 * t]);
            acc[t].x += c * v.x; acc[t].y += c * v.y;
            acc[t].z += c * v.z; acc[t].w += c * v.w;
        }
    }
    float4* md = (float4*)(m + (size_t)w * D);
#pragma unroll
    for (int t = 0; t < NF; t++) md[lane + 32 * t] = acc[t];
}

// ---------------- tensor-core GEMM (3xTF32, pre-split smem) -----------------
// block 128(M) x 64(N), BK=16, 256 threads = 8 warps, warp tile 32x32
#define AS2 20   // A tile row stride in float2 (padded: banks 8g+2t distinct)
#define BS2 68   // B tile row stride in float2 (padded: banks 8t+2g distinct)
#define TG_SMEM (size_t)((2 * 128 * AS2 + 2 * 16 * BS2) * sizeof(float2))

template <int K, bool GELU>
__global__ void __launch_bounds__(256) k_tgemm(
        const float* __restrict__ A, const float* __restrict__ B,
        const float* __restrict__ bias, float* __restrict__ C, int M) {
    const int BM = 128, BN = 64, BK = 16;
    extern __shared__ float2 smem2[];
    float2* As2 = smem2;                 // [2][BM*AS2]
    float2* Bs2 = smem2 + 2 * BM * AS2;  // [2][BK*BS2]

    int bm = blockIdx.x * BM;
    int bn = blockIdx.y * BN;
    int tid = threadIdx.x;
    int wid = tid >> 5, lane = tid & 31;
    int g = lane >> 2, t = lane & 3;
    int warp_m = (wid & 3) * 32;   // 0..96
    int warp_n = (wid >> 2) * 32;  // 0 or 32

    // global load mapping
    int arow = tid >> 1;                        // A tile: 128 rows x 16
    int ac4 = (tid & 1) * 8;                    // 8 floats per thread
    int brow = tid >> 4, bc4 = (tid & 15) * 4;  // B tile: 16 x 64
    const float* Aptr = A + (size_t)(bm + arow) * K + ac4;
    const float* Bptr = B + (size_t)brow * DH + bn + bc4;
    bool aok = (bm + arow) < M;

    float acc[2][4][4];
#pragma unroll
    for (int m = 0; m < 2; m++)
#pragma unroll
        for (int n = 0; n < 4; n++)
#pragma unroll
            for (int c = 0; c < 4; c++) acc[m][n][c] = 0.f;

    // ---- stage 0 fill ----
    {
        float4 a0 = make_float4(0.f, 0.f, 0.f, 0.f), a1 = a0;
        if (aok) { a0 = *(const float4*)Aptr; a1 = *(const float4*)(Aptr + 4); }
        float4 bv = *(const float4*)Bptr;
        float2* as = &As2[arow * AS2 + ac4];
        as[0] = tf32_split2(a0.x); as[1] = tf32_split2(a0.y);
        as[2] = tf32_split2(a0.z); as[3] = tf32_split2(a0.w);
        as[4] = tf32_split2(a1.x); as[5] = tf32_split2(a1.y);
        as[6] = tf32_split2(a1.z); as[7] = tf32_split2(a1.w);
        float2* bs = &Bs2[brow * BS2 + bc4];
        bs[0] = tf32_split2(bv.x); bs[1] = tf32_split2(bv.y);
        bs[2] = tf32_split2(bv.z); bs[3] = tf32_split2(bv.w);
    }
    __syncthreads();

    int buf = 0;
#pragma unroll
    for (int k0 = BK; k0 <= K; k0 += BK) {
        bool more = k0 < K;
        float4 pa0, pa1, pbv;
        if (more) {
            pa0 = make_float4(0.f, 0.f, 0.f, 0.f); pa1 = pa0;
            if (aok) { pa0 = *(const float4*)(Aptr + k0); pa1 = *(const float4*)(Aptr + k0 + 4); }
            pbv = *(const float4*)(Bptr + (size_t)k0 * DH);
        }

        const float2* as = As2 + buf * (BM * AS2);
        const float2* bs = Bs2 + buf * (BK * BS2);
#pragma unroll
        for (int ks = 0; ks < BK; ks += 8) {
            float2 a2[2][4], b2[4][2];
#pragma unroll
            for (int m = 0; m < 2; m++) {
                int r0 = warp_m + m * 16;
                a2[m][0] = as[(r0 + g) * AS2 + ks + t];
                a2[m][1] = as[(r0 + g + 8) * AS2 + ks + t];
                a2[m][2] = as[(r0 + g) * AS2 + ks + t + 4];
                a2[m][3] = as[(r0 + g + 8) * AS2 + ks + t + 4];
            }
#pragma unroll
            for (int n = 0; n < 4; n++) {
                int n0 = warp_n + n * 8 + g;
                b2[n][0] = bs[(ks + t) * BS2 + n0];
                b2[n][1] = bs[(ks + t + 4) * BS2 + n0];
            }
#pragma unroll
            for (int m = 0; m < 2; m++)
#pragma unroll
                for (int n = 0; n < 4; n++) {
                    float* c = acc[m][n];
                    mma_tf32(c[0], c[1], c[2], c[3],
                             a2[m][0].y, a2[m][1].y, a2[m][2].y, a2[m][3].y,
                             b2[n][0].x, b2[n][1].x);
                    mma_tf32(c[0], c[1], c[2], c[3],
                             a2[m][0].x, a2[m][1].x, a2[m][2].x, a2[m][3].x,
                             b2[n][0].y, b2[n][1].y);
                    mma_tf32(c[0], c[1], c[2], c[3],
                             a2[m][0].x, a2[m][1].x, a2[m][2].x, a2[m][3].x,
                             b2[n][0].x, b2[n][1].x);
                }
        }

        if (more) {
            int nb = buf ^ 1;
            float2* asn = &As2[nb * (BM * AS2) + arow * AS2 + ac4];
            asn[0] = tf32_split2(pa0.x); asn[1] = tf32_split2(pa0.y);
            asn[2] = tf32_split2(pa0.z); asn[3] = tf32_split2(pa0.w);
            asn[4] = tf32_split2(pa1.x); asn[5] = tf32_split2(pa1.y);
            asn[6] = tf32_split2(pa1.z); asn[7] = tf32_split2(pa1.w);
            float2* bsn = &Bs2[nb * (BK * BS2) + brow * BS2 + bc4];
            bsn[0] = tf32_split2(pbv.x); bsn[1] = tf32_split2(pbv.y);
            bsn[2] = tf32_split2(pbv.z); bsn[3] = tf32_split2(pbv.w);
            __syncthreads();
            buf = nb;
        }
    }

    // ---- epilogue ----
#pragma unroll
    for (int m = 0; m < 2; m++) {
        int row0 = bm + warp_m + m * 16;
#pragma unroll
        for (int n = 0; n < 4; n++) {
            int col = bn + warp_n + n * 8 + t * 2;
            float b0 = __ldg(&bias[col]), b1 = __ldg(&bias[col + 1]);
            int r = row0 + g;
            if (r < M) {
                float2 o = make_float2(acc[m][n][0] + b0, acc[m][n][1] + b1);
                if (GELU) { o.x = gelu_tanh(o.x); o.y = gelu_tanh(o.y); }
                *(float2*)(C + (size_t)r * DH + col) = o;
            }
            int r2 = row0 + g + 8;
            if (r2 < M) {
                float2 o = make_float2(acc[m][n][2] + b0, acc[m][n][3] + b1);
                if (GELU) { o.x = gelu_tanh(o.x); o.y = gelu_tanh(o.y); }
                *(float2*)(C + (size_t)r2 * DH + col) = o;
            }
        }
    }
}

// ---------------- batchnorm -------------------------------------------------
__global__ void k_zero_stats() {
    int i = blockIdx.x * blockDim.x + threadIdx.x;
    if (i < 2 * DH) g_stats[i] = 0.0;
}

__global__ void k_bn_stats(const float* __restrict__ m) {
    int c = threadIdx.x;  // 256 threads, one per column
    double s = 0.0, ss = 0.0;
    for (int r = blockIdx.x; r < NN; r += gridDim.x) {
        float v = m[(size_t)r * DH + c];
        s += v;
        ss += (double)v * (double)v;
    }
    atomicAdd(&g_stats[c], s);
    atomicAdd(&g_stats[DH + c], ss);
}

__global__ void k_bn_final(const float* __restrict__ gamma, const float* __restrict__ beta) {
    int c = threadIdx.x;
    double mean = g_stats[c] / (double)NN;
    double var = g_stats[DH + c] / (double)NN - mean * mean;
    double sc = (double)gamma[c] / sqrt(var + 1e-5);
    g_scale[c] = (float)sc;
    g_shift[c] = (float)((double)beta[c] - mean * sc);
}

// hout = gelu(m*scale+shift) + res  (res may alias hout)
__global__ void k_bn_apply(const float* __restrict__ m, const float* __restrict__ res,
                           float* __restrict__ hout) {
    int idx = blockIdx.x * blockDim.x + threadIdx.x;  // float4 index
    if (idx >= NN * (DH / 4)) return;
    int c4 = (idx & (DH / 4 - 1)) * 4;
    float4 v = ((const float4*)m)[idx];
    float4 r = ((const float4*)res)[idx];
    float4 o;
    o.x = gelu_tanh(v.x * g_scale[c4 + 0] + g_shift[c4 + 0]) + r.x;
    o.y = gelu_tanh(v.y * g_scale[c4 + 1] + g_shift[c4 + 1]) + r.y;
    o.z = gelu_tanh(v.z * g_scale[c4 + 2] + g_shift[c4 + 2]) + r.z;
    o.w = gelu_tanh(v.w * g_scale[c4 + 3] + g_shift[c4 + 3]) + r.w;
    ((float4*)hout)[idx] = o;
}

// ---------------- head: out[r] = mask[r] ? h[r]·w + b : 0 ------------------
__global__ void k_head(const float* __restrict__ h, const float* __restrict__ w,
                       const float* __restrict__ b, const int* __restrict__ mask,
                       float* __restrict__ out) {
    int gw = (blockIdx.x * blockDim.x + threadIdx.x) >> 5;
    int lane = threadIdx.x & 31;
    if (gw >= NN) return;
    const float4* row = (const float4*)(h + (size_t)gw * DH);
    const float4* w4 = (const float4*)w;
    float s = 0.f;
#pragma unroll
    for (int t = 0; t < 2; t++) {
        int j = lane + t * 32;
        float4 a = row[j];
        float4 ww = __ldg(&w4[j]);
        s += a.x * ww.x + a.y * ww.y + a.z * ww.z + a.w * ww.w;
    }
#pragma unroll
    for (int o = 16; o; o >>= 1) s += __shfl_xor_sync(0xffffffffu, s, o);
    if (lane == 0) out[gw] = (mask[gw] != 0) ? (s + __ldg(&b[0])) : 0.0f;
}

// ---------------- launch -----------------------------------------------------
extern "C" void kernel_launch(void* const* d_in, const int* in_sizes, int n_in,
                              void* d_out, int out_size) {
    const float* x = (const float*)d_in[0];
    const int* ei = (const int*)d_in[1];   // int32
    const int* mask = (const int*)d_in[2]; // bool materialized as int32
    const float* conv_w0 = (const float*)d_in[3];
    const float* conv_b0 = (const float*)d_in[4];
    const float* conv_w1 = (const float*)d_in[5];
    const float* conv_b1 = (const float*)d_in[6];
    const float* conv_w2 = (const float*)d_in[7];
    const float* conv_b2 = (const float*)d_in[8];
    const float* bn_g0 = (const float*)d_in[9];
    const float* bn_b0 = (const float*)d_in[10];
    const float* bn_g1 = (const float*)d_in[11];
    const float* bn_b1 = (const float*)d_in[12];
    const float* bn_g2 = (const float*)d_in[13];
    const float* bn_b2 = (const float*)d_in[14];
    const float* proj_w = (const float*)d_in[15];
    const float* proj_b = (const float*)d_in[16];
    const float* lin_w0 = (const float*)d_in[17];
    const float* lin_b0 = (const float*)d_in[18];
    const float* lin_w1 = (const float*)d_in[19];
    const float* lin_b1 = (const float*)d_in[20];
    const float* head_w = (const float*)d_in[21];
    const float* head_b = (const float*)d_in[22];
    float* out = (float*)d_out;

    const int* src = ei;
    const int* dst = ei + EE;

    float *p_h, *p_m, *p_res, *p_tmp;
    cudaGetSymbolAddress((void**)&p_h, g_h);
    cudaGetSymbolAddress((void**)&p_m, g_m);
    cudaGetSymbolAddress((void**)&p_res, g_res);
    cudaGetSymbolAddress((void**)&p_tmp, g_tmp);

    // opt-in to >48KB dynamic smem (host attribute, not an allocation)
    cudaFuncSetAttribute(k_tgemm<DIN, false>, cudaFuncAttributeMaxDynamicSharedMemorySize, (int)TG_SMEM);
    cudaFuncSetAttribute(k_tgemm<DH, false>, cudaFuncAttributeMaxDynamicSharedMemorySize, (int)TG_SMEM);
    cudaFuncSetAttribute(k_tgemm<DH, true>, cudaFuncAttributeMaxDynamicSharedMemorySize, (int)TG_SMEM);

    const int T = 256;
    dim3 tg_grid((NN + 127) / 128, DH / 64);  // 391 x 4
    int ew4_256 = NN * (DH / 4);
    int gather_blocks = (NN * 32 + T - 1) / T;

    // ---- degrees + CSR (once; reused by all 3 gathers) ----
    k_zero_cnt<<<(NN + T - 1) / T, T>>>();
    k_deg_count<<<(EE + T - 1) / T, T>>>(dst);
    k_deg_final<<<(NN + T - 1) / T, T>>>();
    k_scan<<<1, 1024>>>();
    k_csr_fill<<<(EE + T - 1) / T, T>>>(src, dst);

    // residual projection: res = x @ proj_w + proj_b
    k_tgemm<DIN, false><<<tg_grid, T, TG_SMEM>>>(x, proj_w, proj_b, p_res, NN);

    // ---- GCN layer 0 (input x, D=128) ----
    k_gather<DIN><<<gather_blocks, T>>>(x, p_tmp);
    k_tgemm<DIN, false><<<tg_grid, T, TG_SMEM>>>(p_tmp, conv_w0, conv_b0, p_m, NN);
    k_zero_stats<<<2, T>>>();
    k_bn_stats<<<512, T>>>(p_m);
    k_bn_final<<<1, T>>>(bn_g0, bn_b0);
    k_bn_apply<<<(ew4_256 + T - 1) / T, T>>>(p_m, p_res, p_h);

    // ---- GCN layer 1 ----
    k_gather<DH><<<gather_blocks, T>>>(p_h, p_tmp);
    k_tgemm<DH, false><<<tg_grid, T, TG_SMEM>>>(p_tmp, conv_w1, conv_b1, p_m, NN);
    k_zero_stats<<<2, T>>>();
    k_bn_stats<<<512, T>>>(p_m);
    k_bn_final<<<1, T>>>(bn_g1, bn_b1);
    k_bn_apply<<<(ew4_256 + T - 1) / T, T>>>(p_m, p_h, p_h);

    // ---- GCN layer 2 ----
    k_gather<DH><<<gather_blocks, T>>>(p_h, p_tmp);
    k_tgemm<DH, false><<<tg_grid, T, TG_SMEM>>>(p_tmp, conv_w2, conv_b2, p_m, NN);
    k_zero_stats<<<2, T>>>();
    k_bn_stats<<<512, T>>>(p_m);
    k_bn_final<<<1, T>>>(bn_g2, bn_b2);
    k_bn_apply<<<(ew4_256 + T - 1) / T, T>>>(p_m, p_h, p_h);

    // ---- MLP ----
    k_tgemm<DH, true><<<tg_grid, T, TG_SMEM>>>(p_h, lin_w0, lin_b0, p_m, NN);
    k_tgemm<DH, true><<<tg_grid, T, TG_SMEM>>>(p_m, lin_w1, lin_b1, p_h, NN);

    // ---- head ----
    k_head<<<(NN * 32 + T - 1) / T, T>>>(p_h, head_w, head_b, mask, out);
}

// round 7
// speedup vs baseline: 1.4808x; 1.1581x over previous
#include <cuda_runtime.h>
#include <math.h>

#define NN 50000
#define EE 800000
#define DIN 128
#define DH 256
#define SCAN_B 49  // ceil(NN/1024)

// ---------------- scratch (static device globals; no allocations) -----------
__device__ __align__(16) float g_h[NN * DH];
__device__ __align__(16) float g_m[NN * DH];
__device__ __align__(16) float g_res[NN * DH];
__device__ __align__(16) float g_tmp[NN * DH];
__device__ __align__(16) int   g_cnt[NN];
__device__ __align__(16) int   g_off[NN + 1];
__device__ __align__(16) int   g_cursor[NN];
__device__ __align__(16) int   g_csr[EE];
__device__ __align__(16) int   g_bsum[64];
__device__ __align__(16) int   g_bbase[64];
__device__ __align__(16) float g_isd[NN];   // 1/sqrt(deg)
__device__ __align__(16) float g_id[NN];    // 1/deg
__device__ __align__(16) double g_stats[2 * DH];
__device__ __align__(16) float g_scale[DH];
__device__ __align__(16) float g_shift[DH];

// ---------------- helpers ---------------------------------------------------
__device__ __forceinline__ float gelu_tanh(float x) {
    float x3 = x * x * x;
    return 0.5f * x * (1.0f + tanhf(0.7978845608028654f * (x + 0.044715f * x3)));
}

__device__ __forceinline__ float cvt_tf32f(float f) {
    unsigned u;
    asm("cvt.rna.tf32.f32 %0, %1;" : "=r"(u) : "f"(f));
    return __uint_as_float(u);
}

__device__ __forceinline__ float2 tf32_split2(float f) {
    float hi = cvt_tf32f(f);
    float lo = cvt_tf32f(f - hi);
    return make_float2(hi, lo);
}

__device__ __forceinline__ void mma_tf32(float& c0, float& c1, float& c2, float& c3,
                                         float a0, float a1, float a2, float a3,
                                         float b0, float b1) {
    asm volatile("mma.sync.aligned.m16n8k8.row.col.f32.tf32.tf32.f32 "
                 "{%0,%1,%2,%3},{%4,%5,%6,%7},{%8,%9},{%0,%1,%2,%3};"
                 : "+f"(c0), "+f"(c1), "+f"(c2), "+f"(c3)
                 : "r"(__float_as_uint(a0)), "r"(__float_as_uint(a1)),
                   "r"(__float_as_uint(a2)), "r"(__float_as_uint(a3)),
                   "r"(__float_as_uint(b0)), "r"(__float_as_uint(b1)));
}

// ---------------- degree + CSR ----------------------------------------------
__global__ void k_zero_cnt() {
    int i = blockIdx.x * blockDim.x + threadIdx.x;
    if (i < NN) g_cnt[i] = 0;
}

__global__ void k_deg_count(const int* __restrict__ dst) {
    int e = blockIdx.x * blockDim.x + threadIdx.x;
    if (e < EE) atomicAdd(&g_cnt[dst[e]], 1);
}

__global__ void k_deg_final() {
    int i = blockIdx.x * blockDim.x + threadIdx.x;
    if (i < NN) {
        float d = (float)g_cnt[i] + 1.0f;  // self loop
        g_isd[i] = rsqrtf(d);
        g_id[i] = 1.0f / d;
    }
}

// phase 1: per-block inclusive scan; local result in g_off[i+1], block sum out
__global__ void k_scan1() {
    __shared__ int sm[1024];
    int tid = threadIdx.x;
    int i = blockIdx.x * 1024 + tid;
    int v = (i < NN) ? g_cnt[i] : 0;
    sm[tid] = v;
    __syncthreads();
#pragma unroll
    for (int off = 1; off < 1024; off <<= 1) {
        int t = (tid >= off) ? sm[tid - off] : 0;
        __syncthreads();
        sm[tid] += t;
        __syncthreads();
    }
    if (i < NN) g_off[i + 1] = sm[tid];  // local inclusive (no base yet)
    if (tid == 1023) g_bsum[blockIdx.x] = sm[1023];
}

// phase 2: exclusive scan of block sums (single small block)
__global__ void k_scan2() {
    __shared__ int sm[64];
    int tid = threadIdx.x;  // 64 threads
    int v = (tid < SCAN_B) ? g_bsum[tid] : 0;
    sm[tid] = v;
    __syncthreads();
#pragma unroll
    for (int off = 1; off < 64; off <<= 1) {
        int t = (tid >= off) ? sm[tid - off] : 0;
        __syncthreads();
        sm[tid] += t;
        __syncthreads();
    }
    if (tid < SCAN_B) g_bbase[tid] = sm[tid] - v;  // exclusive base
}

// phase 3: add bases, produce g_off / g_cursor
__global__ void k_scan3() {
    int i = blockIdx.x * 1024 + threadIdx.x;
    if (i < NN) {
        int incl = g_off[i + 1] + g_bbase[blockIdx.x];
        g_off[i + 1] = incl;
        g_cursor[i] = incl - g_cnt[i];
    }
    if (i == 0) g_off[0] = 0;
}

__global__ void k_csr_fill(const int* __restrict__ src, const int* __restrict__ dst) {
    int e = blockIdx.x * blockDim.x + threadIdx.x;
    if (e < EE) {
        int p = atomicAdd(&g_cursor[dst[e]], 1);
        g_csr[p] = src[e];
    }
}

// ---------------- aggregation: warp-per-node CSR gather ---------------------
// m[i] = id_i * h[i] + isd_i * sum_{s->i} isd_s * h[s]
template <int D>
__global__ void k_gather(const float* __restrict__ h, float* __restrict__ m) {
    int w = (blockIdx.x * blockDim.x + threadIdx.x) >> 5;
    int lane = threadIdx.x & 31;
    if (w >= NN) return;
    const int NF = D / 128;  // float4 per lane
    const float4* hn = (const float4*)(h + (size_t)w * D);
    float idg = g_id[w], isdd = g_isd[w];
    float4 acc[NF];
#pragma unroll
    for (int t = 0; t < NF; t++) {
        float4 v = hn[lane + 32 * t];
        acc[t] = make_float4(v.x * idg, v.y * idg, v.z * idg, v.w * idg);
    }
    int e0 = g_off[w], e1 = g_off[w + 1];
    for (int e = e0; e < e1; e++) {
        int s = __ldg(&g_csr[e]);
        float c = isdd * __ldg(&g_isd[s]);
        const float4* hs = (const float4*)(h + (size_t)s * D);
#pragma unroll
        for (int t = 0; t < NF; t++) {
            float4 v = __ldg(&hs[lane + 32 * t]);
            acc[t].x += c * v.x; acc[t].y += c * v.y;
            acc[t].z += c * v.z; acc[t].w += c * v.w;
        }
    }
    float4* md = (float4*)(m + (size_t)w * D);
#pragma unroll
    for (int t = 0; t < NF; t++) md[lane + 32 * t] = acc[t];
}

// ---------------- tensor-core GEMM (3xTF32, pre-split smem) -----------------
// block 128(M) x 64(N), BK=16, 256 threads = 8 warps, warp tile 32x32
// STATS: also accumulate per-column sum / sumsq of the output into g_stats.
#define AS2 20
#define BS2 68
#define TG_SMEM (size_t)((2 * 128 * AS2 + 2 * 16 * BS2) * sizeof(float2))

template <int K, bool GELU, bool STATS>
__global__ void __launch_bounds__(256) k_tgemm(
        const float* __restrict__ A, const float* __restrict__ B,
        const float* __restrict__ bias, float* __restrict__ C, int M) {
    const int BM = 128, BN = 64, BK = 16;
    extern __shared__ float2 smem2[];
    float2* As2 = smem2;                 // [2][BM*AS2]
    float2* Bs2 = smem2 + 2 * BM * AS2;  // [2][BK*BS2]

    int bm = blockIdx.x * BM;
    int bn = blockIdx.y * BN;
    int tid = threadIdx.x;
    int wid = tid >> 5, lane = tid & 31;
    int g = lane >> 2, t = lane & 3;
    int warp_m = (wid & 3) * 32;   // 0..96
    int warp_n = (wid >> 2) * 32;  // 0 or 32

    int arow = tid >> 1;
    int ac4 = (tid & 1) * 8;
    int brow = tid >> 4, bc4 = (tid & 15) * 4;
    const float* Aptr = A + (size_t)(bm + arow) * K + ac4;
    const float* Bptr = B + (size_t)brow * DH + bn + bc4;
    bool aok = (bm + arow) < M;

    float acc[2][4][4];
#pragma unroll
    for (int m = 0; m < 2; m++)
#pragma unroll
        for (int n = 0; n < 4; n++)
#pragma unroll
            for (int c = 0; c < 4; c++) acc[m][n][c] = 0.f;

    {
        float4 a0 = make_float4(0.f, 0.f, 0.f, 0.f), a1 = a0;
        if (aok) { a0 = *(const float4*)Aptr; a1 = *(const float4*)(Aptr + 4); }
        float4 bv = *(const float4*)Bptr;
        float2* as = &As2[arow * AS2 + ac4];
        as[0] = tf32_split2(a0.x); as[1] = tf32_split2(a0.y);
        as[2] = tf32_split2(a0.z); as[3] = tf32_split2(a0.w);
        as[4] = tf32_split2(a1.x); as[5] = tf32_split2(a1.y);
        as[6] = tf32_split2(a1.z); as[7] = tf32_split2(a1.w);
        float2* bs = &Bs2[brow * BS2 + bc4];
        bs[0] = tf32_split2(bv.x); bs[1] = tf32_split2(bv.y);
        bs[2] = tf32_split2(bv.z); bs[3] = tf32_split2(bv.w);
    }
    __syncthreads();

    int buf = 0;
#pragma unroll
    for (int k0 = BK; k0 <= K; k0 += BK) {
        bool more = k0 < K;
        float4 pa0, pa1, pbv;
        if (more) {
            pa0 = make_float4(0.f, 0.f, 0.f, 0.f); pa1 = pa0;
            if (aok) { pa0 = *(const float4*)(Aptr + k0); pa1 = *(const float4*)(Aptr + k0 + 4); }
            pbv = *(const float4*)(Bptr + (size_t)k0 * DH);
        }

        const float2* as = As2 + buf * (BM * AS2);
        const float2* bs = Bs2 + buf * (BK * BS2);
#pragma unroll
        for (int ks = 0; ks < BK; ks += 8) {
            float2 a2[2][4], b2[4][2];
#pragma unroll
            for (int m = 0; m < 2; m++) {
                int r0 = warp_m + m * 16;
                a2[m][0] = as[(r0 + g) * AS2 + ks + t];
                a2[m][1] = as[(r0 + g + 8) * AS2 + ks + t];
                a2[m][2] = as[(r0 + g) * AS2 + ks + t + 4];
                a2[m][3] = as[(r0 + g + 8) * AS2 + ks + t + 4];
            }
#pragma unroll
            for (int n = 0; n < 4; n++) {
                int n0 = warp_n + n * 8 + g;
                b2[n][0] = bs[(ks + t) * BS2 + n0];
                b2[n][1] = bs[(ks + t + 4) * BS2 + n0];
            }
#pragma unroll
            for (int m = 0; m < 2; m++)
#pragma unroll
                for (int n = 0; n < 4; n++) {
                    float* c = acc[m][n];
                    mma_tf32(c[0], c[1], c[2], c[3],
                             a2[m][0].y, a2[m][1].y, a2[m][2].y, a2[m][3].y,
                             b2[n][0].x, b2[n][1].x);
                    mma_tf32(c[0], c[1], c[2], c[3],
                             a2[m][0].x, a2[m][1].x, a2[m][2].x, a2[m][3].x,
                             b2[n][0].y, b2[n][1].y);
                    mma_tf32(c[0], c[1], c[2], c[3],
                             a2[m][0].x, a2[m][1].x, a2[m][2].x, a2[m][3].x,
                             b2[n][0].x, b2[n][1].x);
                }
        }

        if (more) {
            int nb = buf ^ 1;
            float2* asn = &As2[nb * (BM * AS2) + arow * AS2 + ac4];
            asn[0] = tf32_split2(pa0.x); asn[1] = tf32_split2(pa0.y);
            asn[2] = tf32_split2(pa0.z); asn[3] = tf32_split2(pa0.w);
            asn[4] = tf32_split2(pa1.x); asn[5] = tf32_split2(pa1.y);
            asn[6] = tf32_split2(pa1.z); asn[7] = tf32_split2(pa1.w);
            float2* bsn = &Bs2[nb * (BK * BS2) + brow * BS2 + bc4];
            bsn[0] = tf32_split2(pbv.x); bsn[1] = tf32_split2(pbv.y);
            bsn[2] = tf32_split2(pbv.z); bsn[3] = tf32_split2(pbv.w);
            __syncthreads();
            buf = nb;
        }
    }

    // ---- epilogue (store + optional column stats) ----
    float s_sum[4][2], s_sq[4][2];
    if (STATS) {
#pragma unroll
        for (int n = 0; n < 4; n++)
#pragma unroll
            for (int p = 0; p < 2; p++) { s_sum[n][p] = 0.f; s_sq[n][p] = 0.f; }
    }
#pragma unroll
    for (int m = 0; m < 2; m++) {
        int row0 = bm + warp_m + m * 16;
#pragma unroll
        for (int n = 0; n < 4; n++) {
            int col = bn + warp_n + n * 8 + t * 2;
            float b0 = __ldg(&bias[col]), b1 = __ldg(&bias[col + 1]);
            int r = row0 + g;
            if (r < M) {
                float2 o = make_float2(acc[m][n][0] + b0, acc[m][n][1] + b1);
                if (STATS) {
                    s_sum[n][0] += o.x; s_sq[n][0] += o.x * o.x;
                    s_sum[n][1] += o.y; s_sq[n][1] += o.y * o.y;
                }
                if (GELU) { o.x = gelu_tanh(o.x); o.y = gelu_tanh(o.y); }
                *(float2*)(C + (size_t)r * DH + col) = o;
            }
            int r2 = row0 + g + 8;
            if (r2 < M) {
                float2 o = make_float2(acc[m][n][2] + b0, acc[m][n][3] + b1);
                if (STATS) {
                    s_sum[n][0] += o.x; s_sq[n][0] += o.x * o.x;
                    s_sum[n][1] += o.y; s_sq[n][1] += o.y * o.y;
                }
                if (GELU) { o.x = gelu_tanh(o.x); o.y = gelu_tanh(o.y); }
                *(float2*)(C + (size_t)r2 * DH + col) = o;
            }
        }
    }
    if (STATS) {
        // reduce over the 8 lanes (g) sharing each column
#pragma unroll
        for (int n = 0; n < 4; n++)
#pragma unroll
            for (int p = 0; p < 2; p++) {
#pragma unroll
                for (int off = 4; off < 32; off <<= 1) {
                    s_sum[n][p] += __shfl_xor_sync(0xffffffffu, s_sum[n][p], off);
                    s_sq[n][p] += __shfl_xor_sync(0xffffffffu, s_sq[n][p], off);
                }
            }
        if (lane < 4) {  // g == 0 lanes hold totals; t = lane
#pragma unroll
            for (int n = 0; n < 4; n++)
#pragma unroll
                for (int p = 0; p < 2; p++) {
                    int col = bn + warp_n + n * 8 + lane * 2 + p;
                    atomicAdd(&g_stats[col], (double)s_sum[n][p]);
                    atomicAdd(&g_stats[DH + col], (double)s_sq[n][p]);
                }
        }
    }
}

// ---------------- batchnorm -------------------------------------------------
__global__ void k_zero_stats() {
    int i = blockIdx.x * blockDim.x + threadIdx.x;
    if (i < 2 * DH) g_stats[i] = 0.0;
}

__global__ void k_bn_final(const float* __restrict__ gamma, const float* __restrict__ beta) {
    int c = threadIdx.x;
    double mean = g_stats[c] / (double)NN;
    double var = g_stats[DH + c] / (double)NN - mean * mean;
    double sc = (double)gamma[c] / sqrt(var + 1e-5);
    g_scale[c] = (float)sc;
    g_shift[c] = (float)((double)beta[c] - mean * sc);
}

// hout = gelu(m*scale+shift) + res  (res may alias hout)
__global__ void k_bn_apply(const float* __restrict__ m, const float* __restrict__ res,
                           float* __restrict__ hout) {
    int idx = blockIdx.x * blockDim.x + threadIdx.x;  // float4 index
    if (idx >= NN * (DH / 4)) return;
    int c4 = (idx & (DH / 4 - 1)) * 4;
    float4 v = ((const float4*)m)[idx];
    float4 r = ((const float4*)res)[idx];
    float4 o;
    o.x = gelu_tanh(v.x * g_scale[c4 + 0] + g_shift[c4 + 0]) + r.x;
    o.y = gelu_tanh(v.y * g_scale[c4 + 1] + g_shift[c4 + 1]) + r.y;
    o.z = gelu_tanh(v.z * g_scale[c4 + 2] + g_shift[c4 + 2]) + r.z;
    o.w = gelu_tanh(v.w * g_scale[c4 + 3] + g_shift[c4 + 3]) + r.w;
    ((float4*)hout)[idx] = o;
}

// ---------------- head ------------------------------------------------------
__global__ void k_head(const float* __restrict__ h, const float* __restrict__ w,
                       const float* __restrict__ b, const int* __restrict__ mask,
                       float* __restrict__ out) {
    int gw = (blockIdx.x * blockDim.x + threadIdx.x) >> 5;
    int lane = threadIdx.x & 31;
    if (gw >= NN) return;
    const float4* row = (const float4*)(h + (size_t)gw * DH);
    const float4* w4 = (const float4*)w;
    float s = 0.f;
#pragma unroll
    for (int t = 0; t < 2; t++) {
        int j = lane + t * 32;
        float4 a = row[j];
        float4 ww = __ldg(&w4[j]);
        s += a.x * ww.x + a.y * ww.y + a.z * ww.z + a.w * ww.w;
    }
#pragma unroll
    for (int o = 16; o; o >>= 1) s += __shfl_xor_sync(0xffffffffu, s, o);
    if (lane == 0) out[gw] = (mask[gw] != 0) ? (s + __ldg(&b[0])) : 0.0f;
}

// ---------------- launch -----------------------------------------------------
extern "C" void kernel_launch(void* const* d_in, const int* in_sizes, int n_in,
                              void* d_out, int out_size) {
    const float* x = (const float*)d_in[0];
    const int* ei = (const int*)d_in[1];
    const int* mask = (const int*)d_in[2];
    const float* conv_w0 = (const float*)d_in[3];
    const float* conv_b0 = (const float*)d_in[4];
    const float* conv_w1 = (const float*)d_in[5];
    const float* conv_b1 = (const float*)d_in[6];
    const float* conv_w2 = (const float*)d_in[7];
    const float* conv_b2 = (const float*)d_in[8];
    const float* bn_g0 = (const float*)d_in[9];
    const float* bn_b0 = (const float*)d_in[10];
    const float* bn_g1 = (const float*)d_in[11];
    const float* bn_b1 = (const float*)d_in[12];
    const float* bn_g2 = (const float*)d_in[13];
    const float* bn_b2 = (const float*)d_in[14];
    const float* proj_w = (const float*)d_in[15];
    const float* proj_b = (const float*)d_in[16];
    const float* lin_w0 = (const float*)d_in[17];
    const float* lin_b0 = (const float*)d_in[18];
    const float* lin_w1 = (const float*)d_in[19];
    const float* lin_b1 = (const float*)d_in[20];
    const float* head_w = (const float*)d_in[21];
    const float* head_b = (const float*)d_in[22];
    float* out = (float*)d_out;

    const int* src = ei;
    const int* dst = ei + EE;

    float *p_h, *p_m, *p_res, *p_tmp;
    cudaGetSymbolAddress((void**)&p_h, g_h);
    cudaGetSymbolAddress((void**)&p_m, g_m);
    cudaGetSymbolAddress((void**)&p_res, g_res);
    cudaGetSymbolAddress((void**)&p_tmp, g_tmp);

    cudaFuncSetAttribute(k_tgemm<DIN, false, false>, cudaFuncAttributeMaxDynamicSharedMemorySize, (int)TG_SMEM);
    cudaFuncSetAttribute(k_tgemm<DIN, false, true>, cudaFuncAttributeMaxDynamicSharedMemorySize, (int)TG_SMEM);
    cudaFuncSetAttribute(k_tgemm<DH, false, true>, cudaFuncAttributeMaxDynamicSharedMemorySize, (int)TG_SMEM);
    cudaFuncSetAttribute(k_tgemm<DH, true, false>, cudaFuncAttributeMaxDynamicSharedMemorySize, (int)TG_SMEM);

    const int T = 256;
    dim3 tg_grid((NN + 127) / 128, DH / 64);  // 391 x 4
    int ew4_256 = NN * (DH / 4);
    int gather_blocks = (NN * 32 + T - 1) / T;

    // ---- degrees (launches 1-3) ----
    k_zero_cnt<<<(NN + T - 1) / T, T>>>();
    k_deg_count<<<(EE + T - 1) / T, T>>>(dst);
    k_deg_final<<<(NN + T - 1) / T, T>>>();

    // launch 4: proj GEMM (profiled slot)
    k_tgemm<DIN, false, false><<<tg_grid, T, TG_SMEM>>>(x, proj_w, proj_b, p_res, NN);

    // ---- CSR build (parallel scan) ----
    k_scan1<<<SCAN_B, 1024>>>();
    k_scan2<<<1, 64>>>();
    k_scan3<<<SCAN_B, 1024>>>();
    k_csr_fill<<<(EE + T - 1) / T, T>>>(src, dst);

    // ---- GCN layer 0 (input x, D=128) ----
    k_zero_stats<<<2, T>>>();
    k_gather<DIN><<<gather_blocks, T>>>(x, p_tmp);
    k_tgemm<DIN, false, true><<<tg_grid, T, TG_SMEM>>>(p_tmp, conv_w0, conv_b0, p_m, NN);
    k_bn_final<<<1, T>>>(bn_g0, bn_b0);
    k_bn_apply<<<(ew4_256 + T - 1) / T, T>>>(p_m, p_res, p_h);

    // ---- GCN layer 1 ----
    k_zero_stats<<<2, T>>>();
    k_gather<DH><<<gather_blocks, T>>>(p_h, p_tmp);
    k_tgemm<DH, false, true><<<tg_grid, T, TG_SMEM>>>(p_tmp, conv_w1, conv_b1, p_m, NN);
    k_bn_final<<<1, T>>>(bn_g1, bn_b1);
    k_bn_apply<<<(ew4_256 + T - 1) / T, T>>>(p_m, p_h, p_h);

    // ---- GCN layer 2 ----
    k_zero_stats<<<2, T>>>();
    k_gather<DH><<<gather_blocks, T>>>(p_h, p_tmp);
    k_tgemm<DH, false, true><<<tg_grid, T, TG_SMEM>>>(p_tmp, conv_w2, conv_b2, p_m, NN);
    k_bn_final<<<1, T>>>(bn_g2, bn_b2);
    k_bn_apply<<<(ew4_256 + T - 1) / T, T>>>(p_m, p_h, p_h);

    // ---- MLP ----
    k_tgemm<DH, true, false><<<tg_grid, T, TG_SMEM>>>(p_h, lin_w0, lin_b0, p_m, NN);
    k_tgemm<DH, true, false><<<tg_grid, T, TG_SMEM>>>(p_m, lin_w1, lin_b1, p_h, NN);

    // ---- head ----
    k_head<<<(NN * 32 + T - 1) / T, T>>>(p_h, head_w, head_b, mask, out);
}

// round 8
// speedup vs baseline: 2.0269x; 1.3687x over previous
#include <cuda_runtime.h>
#include <cuda_bf16.h>
#include <math.h>

#define NN 50000
#define EE 800000
#define DIN 128
#define DH 256
#define SCAN_B 49  // ceil(NN/1024)

typedef __nv_bfloat16 bf16;
typedef __nv_bfloat162 bf162;

// ---------------- scratch (static device globals; no allocations) -----------
__device__ __align__(16) float g_h[NN * DH];
__device__ __align__(16) float g_m[NN * DH];
__device__ __align__(16) float g_res[NN * DH];
__device__ __align__(16) bf16  g_p1h[NN * DH];
__device__ __align__(16) bf16  g_p1l[NN * DH];
__device__ __align__(16) bf16  g_p2h[NN * DH];
__device__ __align__(16) bf16  g_p2l[NN * DH];
__device__ __align__(16) bf16  g_wh[6 * DH * DH];  // transposed [N][K] hi planes
__device__ __align__(16) bf16  g_wl[6 * DH * DH];
__device__ __align__(16) int   g_cnt[NN];
__device__ __align__(16) int   g_off[NN + 1];
__device__ __align__(16) int   g_cursor[NN];
__device__ __align__(16) int   g_csr[EE];
__device__ __align__(16) int   g_bsum[64];
__device__ __align__(16) int   g_bbase[64];
__device__ __align__(16) float g_isd[NN];
__device__ __align__(16) float g_id[NN];
__device__ __align__(16) double g_stats[2 * DH];
__device__ __align__(16) float g_scale[DH];
__device__ __align__(16) float g_shift[DH];

// ---------------- helpers ---------------------------------------------------
__device__ __forceinline__ float gelu_tanh(float x) {
    float x3 = x * x * x;
    return 0.5f * x * (1.0f + tanhf(0.7978845608028654f * (x + 0.044715f * x3)));
}

__device__ __forceinline__ void bsplit(float x, bf16& h, bf16& l) {
    h = __float2bfloat16_rn(x);
    l = __float2bfloat16_rn(x - __bfloat162float(h));
}

__device__ __forceinline__ void mma_bf16(float& c0, float& c1, float& c2, float& c3,
                                         unsigned a0, unsigned a1, unsigned a2, unsigned a3,
                                         unsigned b0, unsigned b1) {
    asm volatile("mma.sync.aligned.m16n8k16.row.col.f32.bf16.bf16.f32 "
                 "{%0,%1,%2,%3},{%4,%5,%6,%7},{%8,%9},{%0,%1,%2,%3};"
                 : "+f"(c0), "+f"(c1), "+f"(c2), "+f"(c3)
                 : "r"(a0), "r"(a1), "r"(a2), "r"(a3), "r"(b0), "r"(b1));
}

// ---------------- degree + CSR ----------------------------------------------
__global__ void k_zero_cnt() {
    int i = blockIdx.x * blockDim.x + threadIdx.x;
    if (i < NN) g_cnt[i] = 0;
}

__global__ void k_deg_count(const int* __restrict__ dst) {
    int e = blockIdx.x * blockDim.x + threadIdx.x;
    if (e < EE) atomicAdd(&g_cnt[dst[e]], 1);
}

__global__ void k_deg_final() {
    int i = blockIdx.x * blockDim.x + threadIdx.x;
    if (i < NN) {
        float d = (float)g_cnt[i] + 1.0f;
        g_isd[i] = rsqrtf(d);
        g_id[i] = 1.0f / d;
    }
}

__global__ void k_scan1() {
    __shared__ int sm[1024];
    int tid = threadIdx.x;
    int i = blockIdx.x * 1024 + tid;
    int v = (i < NN) ? g_cnt[i] : 0;
    sm[tid] = v;
    __syncthreads();
#pragma unroll
    for (int off = 1; off < 1024; off <<= 1) {
        int t = (tid >= off) ? sm[tid - off] : 0;
        __syncthreads();
        sm[tid] += t;
        __syncthreads();
    }
    if (i < NN) g_off[i + 1] = sm[tid];
    if (tid == 1023) g_bsum[blockIdx.x] = sm[1023];
}

__global__ void k_scan2() {
    __shared__ int sm[64];
    int tid = threadIdx.x;
    int v = (tid < SCAN_B) ? g_bsum[tid] : 0;
    sm[tid] = v;
    __syncthreads();
#pragma unroll
    for (int off = 1; off < 64; off <<= 1) {
        int t = (tid >= off) ? sm[tid - off] : 0;
        __syncthreads();
        sm[tid] += t;
        __syncthreads();
    }
    if (tid < SCAN_B) g_bbase[tid] = sm[tid] - v;
}

__global__ void k_scan3() {
    int i = blockIdx.x * 1024 + threadIdx.x;
    if (i < NN) {
        int incl = g_off[i + 1] + g_bbase[blockIdx.x];
        g_off[i + 1] = incl;
        g_cursor[i] = incl - g_cnt[i];
    }
    if (i == 0) g_off[0] = 0;
}

__global__ void k_csr_fill(const int* __restrict__ src, const int* __restrict__ dst) {
    int e = blockIdx.x * blockDim.x + threadIdx.x;
    if (e < EE) {
        int p = atomicAdd(&g_cursor[dst[e]], 1);
        g_csr[p] = src[e];
    }
}

// ---------------- splitting producers ---------------------------------------
// x -> bf16 hi/lo planes
__global__ void k_split_x(const float* __restrict__ x, bf16* __restrict__ oh,
                          bf16* __restrict__ ol) {
    int idx = blockIdx.x * blockDim.x + threadIdx.x;  // float4 index
    if (idx >= NN * (DIN / 4)) return;
    float4 v = ((const float4*)x)[idx];
    bf16 h0, l0, h1, l1, h2, l2, h3, l3;
    bsplit(v.x, h0, l0); bsplit(v.y, h1, l1);
    bsplit(v.z, h2, l2); bsplit(v.w, h3, l3);
    ((bf162*)oh)[idx * 2 + 0] = bf162{h0, h1};
    ((bf162*)oh)[idx * 2 + 1] = bf162{h2, h3};
    ((bf162*)ol)[idx * 2 + 0] = bf162{l0, l1};
    ((bf162*)ol)[idx * 2 + 1] = bf162{l2, l3};
}

// W[K x 256] fp32 -> transposed planes [256][K] bf16
__global__ void k_split_w(const float* __restrict__ W, int K,
                          bf16* __restrict__ oh, bf16* __restrict__ ol) {
    int idx = blockIdx.x * blockDim.x + threadIdx.x;
    if (idx >= K * DH) return;
    int k = idx / DH, n = idx % DH;
    bf16 h, l;
    bsplit(W[idx], h, l);
    oh[n * K + k] = h;
    ol[n * K + k] = l;
}

// ---------------- aggregation: warp-per-node CSR gather -> planes -----------
template <int D>
__global__ void k_gather(const float* __restrict__ h, bf16* __restrict__ oh,
                         bf16* __restrict__ ol) {
    int w = (blockIdx.x * blockDim.x + threadIdx.x) >> 5;
    int lane = threadIdx.x & 31;
    if (w >= NN) return;
    const int NF = D / 128;
    const float4* hn = (const float4*)(h + (size_t)w * D);
    float idg = g_id[w], isdd = g_isd[w];
    float4 acc[NF];
#pragma unroll
    for (int t = 0; t < NF; t++) {
        float4 v = hn[lane + 32 * t];
        acc[t] = make_float4(v.x * idg, v.y * idg, v.z * idg, v.w * idg);
    }
    int e0 = g_off[w], e1 = g_off[w + 1];
    for (int e = e0; e < e1; e++) {
        int s = __ldg(&g_csr[e]);
        float c = isdd * __ldg(&g_isd[s]);
        const float4* hs = (const float4*)(h + (size_t)s * D);
#pragma unroll
        for (int t = 0; t < NF; t++) {
            float4 v = __ldg(&hs[lane + 32 * t]);
            acc[t].x += c * v.x; acc[t].y += c * v.y;
            acc[t].z += c * v.z; acc[t].w += c * v.w;
        }
    }
#pragma unroll
    for (int t = 0; t < NF; t++) {
        int i4 = w * (D / 4) + lane + 32 * t;  // float4 index
        bf16 h0, l0, h1, l1, h2, l2, h3, l3;
        bsplit(acc[t].x, h0, l0); bsplit(acc[t].y, h1, l1);
        bsplit(acc[t].z, h2, l2); bsplit(acc[t].w, h3, l3);
        ((bf162*)oh)[i4 * 2 + 0] = bf162{h0, h1};
        ((bf162*)oh)[i4 * 2 + 1] = bf162{h2, h3};
        ((bf162*)ol)[i4 * 2 + 0] = bf162{l0, l1};
        ((bf162*)ol)[i4 * 2 + 1] = bf162{l2, l3};
    }
}

// ---------------- bf16x2 tensor-core GEMM -----------------------------------
// C[M x 256] = (Ah+Al)[M x K] @ (Bh+Bl)^T  (B planes are [N][K] transposed)
// block 128(M) x 64(N), BK=16, 256 threads, 8 warps, warp tile 32x32.
#define SK 24  // smem row stride in bf16 (48B; conflict-free: row*12+t covers all banks)

template <int K, bool GELU, bool STATS, bool PLANES>
__global__ void __launch_bounds__(256) k_bgemm(
        const bf16* __restrict__ Ah, const bf16* __restrict__ Al,
        const bf16* __restrict__ BhT, const bf16* __restrict__ BlT,
        const float* __restrict__ bias, float* __restrict__ C,
        bf16* __restrict__ Ch, bf16* __restrict__ Cl, int M) {
    const int BM = 128, BN = 64, BK = 16;
    __shared__ bf16 As[2][2][BM * SK];  // [stage][plane]
    __shared__ bf16 Bs[2][2][BN * SK];

    int bm = blockIdx.x * BM;
    int bn = blockIdx.y * BN;
    int tid = threadIdx.x;
    int wid = tid >> 5, lane = tid & 31;
    int g = lane >> 2, t = lane & 3;
    int warp_m = (wid & 3) * 32;
    int warp_n = (wid >> 2) * 32;

    // global load mapping
    int arow = tid >> 1, ahalf = (tid & 1) * 8;      // A: 128 rows, 2x8 bf16 per row
    int bseg = tid >> 1;
    int bplane = bseg >> 6, bno = bseg & 63;
    int bhalf = (tid & 1) * 8;
    const bf16* aptr_h = Ah + (size_t)(bm + arow) * K + ahalf;
    const bf16* aptr_l = Al + (size_t)(bm + arow) * K + ahalf;
    const bf16* bptr = (bplane ? BlT : BhT) + (size_t)(bn + bno) * K + bhalf;
    bool aok = (bm + arow) < M;
    uint4 zero4 = make_uint4(0, 0, 0, 0);

    float acc[2][4][4];
#pragma unroll
    for (int m = 0; m < 2; m++)
#pragma unroll
        for (int n = 0; n < 4; n++)
#pragma unroll
            for (int c = 0; c < 4; c++) acc[m][n][c] = 0.f;

    // stage 0 fill
    {
        uint4 vh = aok ? *(const uint4*)aptr_h : zero4;
        uint4 vl = aok ? *(const uint4*)aptr_l : zero4;
        uint4 vb = *(const uint4*)bptr;
        *(uint4*)&As[0][0][arow * SK + ahalf] = vh;
        *(uint4*)&As[0][1][arow * SK + ahalf] = vl;
        *(uint4*)&Bs[0][bplane][bno * SK + bhalf] = vb;
    }
    __syncthreads();

    int buf = 0;
#pragma unroll
    for (int k0 = BK; k0 <= K; k0 += BK) {
        bool more = k0 < K;
        uint4 pvh, pvl, pvb;
        if (more) {
            pvh = aok ? *(const uint4*)(aptr_h + k0) : zero4;
            pvl = aok ? *(const uint4*)(aptr_l + k0) : zero4;
            pvb = *(const uint4*)(bptr + k0);
        }

        const bf16* ash = As[buf][0];
        const bf16* asl = As[buf][1];
        const bf16* bsh = Bs[buf][0];
        const bf16* bsl = Bs[buf][1];

        unsigned aH[2][4], aL[2][4], bH[4][2], bL[4][2];
#pragma unroll
        for (int m = 0; m < 2; m++) {
            int r1 = (warp_m + m * 16 + g) * SK;
            int r2 = r1 + 8 * SK;
            aH[m][0] = *(const unsigned*)(ash + r1 + 2 * t);
            aH[m][1] = *(const unsigned*)(ash + r2 + 2 * t);
            aH[m][2] = *(const unsigned*)(ash + r1 + 8 + 2 * t);
            aH[m][3] = *(const unsigned*)(ash + r2 + 8 + 2 * t);
            aL[m][0] = *(const unsigned*)(asl + r1 + 2 * t);
            aL[m][1] = *(const unsigned*)(asl + r2 + 2 * t);
            aL[m][2] = *(const unsigned*)(asl + r1 + 8 + 2 * t);
            aL[m][3] = *(const unsigned*)(asl + r2 + 8 + 2 * t);
        }
#pragma unroll
        for (int n = 0; n < 4; n++) {
            int cb = (warp_n + n * 8 + g) * SK;
            bH[n][0] = *(const unsigned*)(bsh + cb + 2 * t);
            bH[n][1] = *(const unsigned*)(bsh + cb + 8 + 2 * t);
            bL[n][0] = *(const unsigned*)(bsl + cb + 2 * t);
            bL[n][1] = *(const unsigned*)(bsl + cb + 8 + 2 * t);
        }
#pragma unroll
        for (int m = 0; m < 2; m++)
#pragma unroll
            for (int n = 0; n < 4; n++) {
                float* c = acc[m][n];
                mma_bf16(c[0], c[1], c[2], c[3],
                         aH[m][0], aH[m][1], aH[m][2], aH[m][3], bL[n][0], bL[n][1]);
                mma_bf16(c[0], c[1], c[2], c[3],
                         aL[m][0], aL[m][1], aL[m][2], aL[m][3], bH[n][0], bH[n][1]);
                mma_bf16(c[0], c[1], c[2], c[3],
                         aH[m][0], aH[m][1], aH[m][2], aH[m][3], bH[n][0], bH[n][1]);
            }

        if (more) {
            int nb = buf ^ 1;
            *(uint4*)&As[nb][0][arow * SK + ahalf] = pvh;
            *(uint4*)&As[nb][1][arow * SK + ahalf] = pvl;
            *(uint4*)&Bs[nb][bplane][bno * SK + bhalf] = pvb;
            __syncthreads();
            buf = nb;
        }
    }

    // ---- epilogue ----
    float s_sum[4][2], s_sq[4][2];
    if (STATS) {
#pragma unroll
        for (int n = 0; n < 4; n++)
#pragma unroll
            for (int p = 0; p < 2; p++) { s_sum[n][p] = 0.f; s_sq[n][p] = 0.f; }
    }
#pragma unroll
    for (int m = 0; m < 2; m++) {
        int row0 = bm + warp_m + m * 16;
#pragma unroll
        for (int n = 0; n < 4; n++) {
            int col = bn + warp_n + n * 8 + t * 2;
            float b0 = __ldg(&bias[col]), b1 = __ldg(&bias[col + 1]);
#pragma unroll
            for (int half = 0; half < 2; half++) {
                int r = row0 + g + half * 8;
                if (r >= M) continue;
                float2 o = make_float2(acc[m][n][half * 2 + 0] + b0,
                                       acc[m][n][half * 2 + 1] + b1);
                if (STATS) {
                    s_sum[n][0] += o.x; s_sq[n][0] += o.x * o.x;
                    s_sum[n][1] += o.y; s_sq[n][1] += o.y * o.y;
                }
                if (GELU) { o.x = gelu_tanh(o.x); o.y = gelu_tanh(o.y); }
                if (PLANES) {
                    bf16 h0, l0, h1, l1;
                    bsplit(o.x, h0, l0); bsplit(o.y, h1, l1);
                    *(bf162*)(Ch + (size_t)r * DH + col) = bf162{h0, h1};
                    *(bf162*)(Cl + (size_t)r * DH + col) = bf162{l0, l1};
                } else {
                    *(float2*)(C + (size_t)r * DH + col) = o;
                }
            }
        }
    }
    if (STATS) {
#pragma unroll
        for (int n = 0; n < 4; n++)
#pragma unroll
            for (int p = 0; p < 2; p++) {
#pragma unroll
                for (int off = 4; off < 32; off <<= 1) {
                    s_sum[n][p] += __shfl_xor_sync(0xffffffffu, s_sum[n][p], off);
                    s_sq[n][p] += __shfl_xor_sync(0xffffffffu, s_sq[n][p], off);
                }
            }
        if (lane < 4) {
#pragma unroll
            for (int n = 0; n < 4; n++)
#pragma unroll
                for (int p = 0; p < 2; p++) {
                    int col = bn + warp_n + n * 8 + lane * 2 + p;
                    atomicAdd(&g_stats[col], (double)s_sum[n][p]);
                    atomicAdd(&g_stats[DH + col], (double)s_sq[n][p]);
                }
        }
    }
}

// ---------------- batchnorm -------------------------------------------------
__global__ void k_zero_stats() {
    int i = blockIdx.x * blockDim.x + threadIdx.x;
    if (i < 2 * DH) g_stats[i] = 0.0;
}

__global__ void k_bn_final(const float* __restrict__ gamma, const float* __restrict__ beta) {
    int c = threadIdx.x;
    double mean = g_stats[c] / (double)NN;
    double var = g_stats[DH + c] / (double)NN - mean * mean;
    double sc = (double)gamma[c] / sqrt(var + 1e-5);
    g_scale[c] = (float)sc;
    g_shift[c] = (float)((double)beta[c] - mean * sc);
}

// MODE 0: fp32 out; MODE 1: bf16 planes out only
template <int MODE>
__global__ void k_bn_apply(const float* __restrict__ m, const float* __restrict__ res,
                           float* __restrict__ hout, bf16* __restrict__ oh,
                           bf16* __restrict__ ol) {
    int idx = blockIdx.x * blockDim.x + threadIdx.x;  // float4 index
    if (idx >= NN * (DH / 4)) return;
    int c4 = (idx & (DH / 4 - 1)) * 4;
    float4 v = ((const float4*)m)[idx];
    float4 r = ((const float4*)res)[idx];
    float4 o;
    o.x = gelu_tanh(v.x * g_scale[c4 + 0] + g_shift[c4 + 0]) + r.x;
    o.y = gelu_tanh(v.y * g_scale[c4 + 1] + g_shift[c4 + 1]) + r.y;
    o.z = gelu_tanh(v.z * g_scale[c4 + 2] + g_shift[c4 + 2]) + r.z;
    o.w = gelu_tanh(v.w * g_scale[c4 + 3] + g_shift[c4 + 3]) + r.w;
    if (MODE == 0) {
        ((float4*)hout)[idx] = o;
    } else {
        bf16 h0, l0, h1, l1, h2, l2, h3, l3;
        bsplit(o.x, h0, l0); bsplit(o.y, h1, l1);
        bsplit(o.z, h2, l2); bsplit(o.w, h3, l3);
        ((bf162*)oh)[idx * 2 + 0] = bf162{h0, h1};
        ((bf162*)oh)[idx * 2 + 1] = bf162{h2, h3};
        ((bf162*)ol)[idx * 2 + 0] = bf162{l0, l1};
        ((bf162*)ol)[idx * 2 + 1] = bf162{l2, l3};
    }
}

// ---------------- head ------------------------------------------------------
__global__ void k_head(const float* __restrict__ h, const float* __restrict__ w,
                       const float* __restrict__ b, const int* __restrict__ mask,
                       float* __restrict__ out) {
    int gw = (blockIdx.x * blockDim.x + threadIdx.x) >> 5;
    int lane = threadIdx.x & 31;
    if (gw >= NN) return;
    const float4* row = (const float4*)(h + (size_t)gw * DH);
    const float4* w4 = (const float4*)w;
    float s = 0.f;
#pragma unroll
    for (int t = 0; t < 2; t++) {
        int j = lane + t * 32;
        float4 a = row[j];
        float4 ww = __ldg(&w4[j]);
        s += a.x * ww.x + a.y * ww.y + a.z * ww.z + a.w * ww.w;
    }
#pragma unroll
    for (int o = 16; o; o >>= 1) s += __shfl_xor_sync(0xffffffffu, s, o);
    if (lane == 0) out[gw] = (mask[gw] != 0) ? (s + __ldg(&b[0])) : 0.0f;
}

// ---------------- launch -----------------------------------------------------
extern "C" void kernel_launch(void* const* d_in, const int* in_sizes, int n_in,
                              void* d_out, int out_size) {
    const float* x = (const float*)d_in[0];
    const int* ei = (const int*)d_in[1];
    const int* mask = (const int*)d_in[2];
    const float* conv_w0 = (const float*)d_in[3];
    const float* conv_b0 = (const float*)d_in[4];
    const float* conv_w1 = (const float*)d_in[5];
    const float* conv_b1 = (const float*)d_in[6];
    const float* conv_w2 = (const float*)d_in[7];
    const float* conv_b2 = (const float*)d_in[8];
    const float* bn_g0 = (const float*)d_in[9];
    const float* bn_b0 = (const float*)d_in[10];
    const float* bn_g1 = (const float*)d_in[11];
    const float* bn_b1 = (const float*)d_in[12];
    const float* bn_g2 = (const float*)d_in[13];
    const float* bn_b2 = (const float*)d_in[14];
    const float* proj_w = (const float*)d_in[15];
    const float* proj_b = (const float*)d_in[16];
    const float* lin_w0 = (const float*)d_in[17];
    const float* lin_b0 = (const float*)d_in[18];
    const float* lin_w1 = (const float*)d_in[19];
    const float* lin_b1 = (const float*)d_in[20];
    const float* head_w = (const float*)d_in[21];
    const float* head_b = (const float*)d_in[22];
    float* out = (float*)d_out;

    const int* src = ei;
    const int* dst = ei + EE;

    float *p_h, *p_m, *p_res;
    bf16 *p1h, *p1l, *p2h, *p2l, *wh, *wl;
    cudaGetSymbolAddress((void**)&p_h, g_h);
    cudaGetSymbolAddress((void**)&p_m, g_m);
    cudaGetSymbolAddress((void**)&p_res, g_res);
    cudaGetSymbolAddress((void**)&p1h, g_p1h);
    cudaGetSymbolAddress((void**)&p1l, g_p1l);
    cudaGetSymbolAddress((void**)&p2h, g_p2h);
    cudaGetSymbolAddress((void**)&p2l, g_p2l);
    cudaGetSymbolAddress((void**)&wh, g_wh);
    cudaGetSymbolAddress((void**)&wl, g_wl);

    const int T = 256;
    const int WSTRIDE = DH * DH;  // 65536 per weight slot
    dim3 tg_grid((NN + 127) / 128, DH / 64);  // 391 x 4
    int ew4_256 = NN * (DH / 4);
    int gather_blocks = (NN * 32 + T - 1) / T;

    // ---- degrees ----
    k_zero_cnt<<<(NN + T - 1) / T, T>>>();
    k_deg_count<<<(EE + T - 1) / T, T>>>(dst);
    k_deg_final<<<(NN + T - 1) / T, T>>>();

    // ---- split inputs + weights into bf16 planes ----
    k_split_x<<<(NN * DIN / 4 + T - 1) / T, T>>>(x, p1h, p1l);
    k_split_w<<<(DIN * DH + T - 1) / T, T>>>(proj_w, DIN, wh + 0 * WSTRIDE, wl + 0 * WSTRIDE);
    k_split_w<<<(DIN * DH + T - 1) / T, T>>>(conv_w0, DIN, wh + 1 * WSTRIDE, wl + 1 * WSTRIDE);
    k_split_w<<<(DH * DH + T - 1) / T, T>>>(conv_w1, DH, wh + 2 * WSTRIDE, wl + 2 * WSTRIDE);
    k_split_w<<<(DH * DH + T - 1) / T, T>>>(conv_w2, DH, wh + 3 * WSTRIDE, wl + 3 * WSTRIDE);
    k_split_w<<<(DH * DH + T - 1) / T, T>>>(lin_w0, DH, wh + 4 * WSTRIDE, wl + 4 * WSTRIDE);
    k_split_w<<<(DH * DH + T - 1) / T, T>>>(lin_w1, DH, wh + 5 * WSTRIDE, wl + 5 * WSTRIDE);

    // ---- CSR build ----
    k_scan1<<<SCAN_B, 1024>>>();
    k_scan2<<<1, 64>>>();
    k_scan3<<<SCAN_B, 1024>>>();
    k_csr_fill<<<(EE + T - 1) / T, T>>>(src, dst);

    // residual projection: res = x @ proj_w + proj_b
    k_bgemm<DIN, false, false, false><<<tg_grid, T>>>(
        p1h, p1l, wh + 0 * WSTRIDE, wl + 0 * WSTRIDE, proj_b, p_res, nullptr, nullptr, NN);

    // ---- GCN layer 0 ----
    k_zero_stats<<<2, T>>>();
    k_gather<DIN><<<gather_blocks, T>>>(x, p2h, p2l);
    k_bgemm<DIN, false, true, false><<<tg_grid, T>>>(
        p2h, p2l, wh + 1 * WSTRIDE, wl + 1 * WSTRIDE, conv_b0, p_m, nullptr, nullptr, NN);
    k_bn_final<<<1, T>>>(bn_g0, bn_b0);
    k_bn_apply<0><<<(ew4_256 + T - 1) / T, T>>>(p_m, p_res, p_h, nullptr, nullptr);

    // ---- GCN layer 1 ----
    k_zero_stats<<<2, T>>>();
    k_gather<DH><<<gather_blocks, T>>>(p_h, p2h, p2l);
    k_bgemm<DH, false, true, false><<<tg_grid, T>>>(
        p2h, p2l, wh + 2 * WSTRIDE, wl + 2 * WSTRIDE, conv_b1, p_m, nullptr, nullptr, NN);
    k_bn_final<<<1, T>>>(bn_g1, bn_b1);
    k_bn_apply<0><<<(ew4_256 + T - 1) / T, T>>>(p_m, p_h, p_h, nullptr, nullptr);

    // ---- GCN layer 2 ----
    k_zero_stats<<<2, T>>>();
    k_gather<DH><<<gather_blocks, T>>>(p_h, p2h, p2l);
    k_bgemm<DH, false, true, false><<<tg_grid, T>>>(
        p2h, p2l, wh + 3 * WSTRIDE, wl + 3 * WSTRIDE, conv_b2, p_m, nullptr, nullptr, NN);
    k_bn_final<<<1, T>>>(bn_g2, bn_b2);
    k_bn_apply<1><<<(ew4_256 + T - 1) / T, T>>>(p_m, p_h, nullptr, p1h, p1l);

    // ---- MLP ----
    k_bgemm<DH, true, false, true><<<tg_grid, T>>>(
        p1h, p1l, wh + 4 * WSTRIDE, wl + 4 * WSTRIDE, lin_b0, nullptr, p2h, p2l, NN);
    k_bgemm<DH, true, false, false><<<tg_grid, T>>>(
        p2h, p2l, wh + 5 * WSTRIDE, wl + 5 * WSTRIDE, lin_b1, p_h, nullptr, nullptr, NN);

    // ---- head ----
    k_head<<<(NN * 32 + T - 1) / T, T>>>(p_h, head_w, head_b, mask, out);
}

// round 9
// speedup vs baseline: 2.3071x; 1.1383x over previous
#include <cuda_runtime.h>
#include <cuda_bf16.h>
#include <math.h>

#define NN 50000
#define EE 800000
#define DIN 128
#define DH 256
#define SCAN_B 49  // ceil(NN/1024)

typedef __nv_bfloat16 bf16;
typedef __nv_bfloat162 bf162;

// ---------------- scratch (static device globals; no allocations) -----------
__device__ __align__(16) float g_h[NN * DH];
__device__ __align__(16) float g_m[NN * DH];
__device__ __align__(16) float g_res[NN * DH];
__device__ __align__(16) bf16  g_p1h[NN * DH];
__device__ __align__(16) bf16  g_p1l[NN * DH];
__device__ __align__(16) bf16  g_p2h[NN * DH];
__device__ __align__(16) bf16  g_p2l[NN * DH];
__device__ __align__(16) bf16  g_wh[6 * DH * DH];  // transposed [N][K] hi planes
__device__ __align__(16) bf16  g_wl[6 * DH * DH];
__device__ __align__(16) int   g_cnt[NN];
__device__ __align__(16) int   g_off[NN + 1];
__device__ __align__(16) int   g_cursor[NN];
__device__ __align__(16) int   g_csr[EE];
__device__ __align__(16) int   g_bsum[64];
__device__ __align__(16) int   g_bbase[64];
__device__ __align__(16) float g_isd[NN];
__device__ __align__(16) float g_id[NN];
__device__ __align__(16) double g_stats[2 * DH];
__device__ __align__(16) float g_scale[DH];
__device__ __align__(16) float g_shift[DH];

// ---------------- helpers ---------------------------------------------------
__device__ __forceinline__ float gelu_tanh(float x) {
    float x3 = x * x * x;
    return 0.5f * x * (1.0f + tanhf(0.7978845608028654f * (x + 0.044715f * x3)));
}

__device__ __forceinline__ void bsplit(float x, bf16& h, bf16& l) {
    h = __float2bfloat16_rn(x);
    l = __float2bfloat16_rn(x - __bfloat162float(h));
}

__device__ __forceinline__ void mma_bf16(float& c0, float& c1, float& c2, float& c3,
                                         unsigned a0, unsigned a1, unsigned a2, unsigned a3,
                                         unsigned b0, unsigned b1) {
    asm volatile("mma.sync.aligned.m16n8k16.row.col.f32.bf16.bf16.f32 "
                 "{%0,%1,%2,%3},{%4,%5,%6,%7},{%8,%9},{%0,%1,%2,%3};"
                 : "+f"(c0), "+f"(c1), "+f"(c2), "+f"(c3)
                 : "r"(a0), "r"(a1), "r"(a2), "r"(a3), "r"(b0), "r"(b1));
}

// ---------------- degree + CSR ----------------------------------------------
__global__ void k_zero_cnt() {
    int i = blockIdx.x * blockDim.x + threadIdx.x;
    if (i < NN) g_cnt[i] = 0;
}

__global__ void k_deg_count(const int* __restrict__ dst) {
    int e = blockIdx.x * blockDim.x + threadIdx.x;
    if (e < EE) atomicAdd(&g_cnt[dst[e]], 1);
}

__global__ void k_deg_final() {
    int i = blockIdx.x * blockDim.x + threadIdx.x;
    if (i < NN) {
        float d = (float)g_cnt[i] + 1.0f;
        g_isd[i] = rsqrtf(d);
        g_id[i] = 1.0f / d;
    }
}

__global__ void k_scan1() {
    __shared__ int sm[1024];
    int tid = threadIdx.x;
    int i = blockIdx.x * 1024 + tid;
    int v = (i < NN) ? g_cnt[i] : 0;
    sm[tid] = v;
    __syncthreads();
#pragma unroll
    for (int off = 1; off < 1024; off <<= 1) {
        int t = (tid >= off) ? sm[tid - off] : 0;
        __syncthreads();
        sm[tid] += t;
        __syncthreads();
    }
    if (i < NN) g_off[i + 1] = sm[tid];
    if (tid == 1023) g_bsum[blockIdx.x] = sm[1023];
}

__global__ void k_scan2() {
    __shared__ int sm[64];
    int tid = threadIdx.x;
    int v = (tid < SCAN_B) ? g_bsum[tid] : 0;
    sm[tid] = v;
    __syncthreads();
#pragma unroll
    for (int off = 1; off < 64; off <<= 1) {
        int t = (tid >= off) ? sm[tid - off] : 0;
        __syncthreads();
        sm[tid] += t;
        __syncthreads();
    }
    if (tid < SCAN_B) g_bbase[tid] = sm[tid] - v;
}

__global__ void k_scan3() {
    int i = blockIdx.x * 1024 + threadIdx.x;
    if (i < NN) {
        int incl = g_off[i + 1] + g_bbase[blockIdx.x];
        g_off[i + 1] = incl;
        g_cursor[i] = incl - g_cnt[i];
    }
    if (i == 0) g_off[0] = 0;
}

__global__ void k_csr_fill(const int* __restrict__ src, const int* __restrict__ dst) {
    int e = blockIdx.x * blockDim.x + threadIdx.x;
    if (e < EE) {
        int p = atomicAdd(&g_cursor[dst[e]], 1);
        g_csr[p] = src[e];
    }
}

// ---------------- splitting producers ---------------------------------------
__global__ void k_split_x(const float* __restrict__ x, bf16* __restrict__ oh,
                          bf16* __restrict__ ol) {
    int idx = blockIdx.x * blockDim.x + threadIdx.x;  // float4 index
    if (idx >= NN * (DIN / 4)) return;
    float4 v = ((const float4*)x)[idx];
    bf16 h0, l0, h1, l1, h2, l2, h3, l3;
    bsplit(v.x, h0, l0); bsplit(v.y, h1, l1);
    bsplit(v.z, h2, l2); bsplit(v.w, h3, l3);
    ((bf162*)oh)[idx * 2 + 0] = bf162{h0, h1};
    ((bf162*)oh)[idx * 2 + 1] = bf162{h2, h3};
    ((bf162*)ol)[idx * 2 + 0] = bf162{l0, l1};
    ((bf162*)ol)[idx * 2 + 1] = bf162{l2, l3};
}

__global__ void k_split_w(const float* __restrict__ W, int K,
                          bf16* __restrict__ oh, bf16* __restrict__ ol) {
    int idx = blockIdx.x * blockDim.x + threadIdx.x;
    if (idx >= K * DH) return;
    int k = idx / DH, n = idx % DH;
    bf16 h, l;
    bsplit(W[idx], h, l);
    oh[n * K + k] = h;
    ol[n * K + k] = l;
}

// ---------------- aggregation: warp-per-node CSR gather -> planes -----------
template <int D>
__global__ void k_gather(const float* __restrict__ h, bf16* __restrict__ oh,
                         bf16* __restrict__ ol) {
    int w = (blockIdx.x * blockDim.x + threadIdx.x) >> 5;
    int lane = threadIdx.x & 31;
    if (w >= NN) return;
    const int NF = D / 128;
    const float4* hn = (const float4*)(h + (size_t)w * D);
    float idg = g_id[w], isdd = g_isd[w];
    float4 acc[NF];
#pragma unroll
    for (int t = 0; t < NF; t++) {
        float4 v = hn[lane + 32 * t];
        acc[t] = make_float4(v.x * idg, v.y * idg, v.z * idg, v.w * idg);
    }
    int e0 = g_off[w], e1 = g_off[w + 1];
    int e = e0;
#pragma unroll 1
    for (; e + 2 <= e1; e += 2) {
        int s0 = __ldg(&g_csr[e]);
        int s1 = __ldg(&g_csr[e + 1]);
        float c0 = isdd * __ldg(&g_isd[s0]);
        float c1 = isdd * __ldg(&g_isd[s1]);
        const float4* h0 = (const float4*)(h + (size_t)s0 * D);
        const float4* h1 = (const float4*)(h + (size_t)s1 * D);
#pragma unroll
        for (int t = 0; t < NF; t++) {
            float4 v0 = __ldg(&h0[lane + 32 * t]);
            float4 v1 = __ldg(&h1[lane + 32 * t]);
            acc[t].x += c0 * v0.x + c1 * v1.x;
            acc[t].y += c0 * v0.y + c1 * v1.y;
            acc[t].z += c0 * v0.z + c1 * v1.z;
            acc[t].w += c0 * v0.w + c1 * v1.w;
        }
    }
    if (e < e1) {
        int s0 = __ldg(&g_csr[e]);
        float c0 = isdd * __ldg(&g_isd[s0]);
        const float4* h0 = (const float4*)(h + (size_t)s0 * D);
#pragma unroll
        for (int t = 0; t < NF; t++) {
            float4 v0 = __ldg(&h0[lane + 32 * t]);
            acc[t].x += c0 * v0.x; acc[t].y += c0 * v0.y;
            acc[t].z += c0 * v0.z; acc[t].w += c0 * v0.w;
        }
    }
#pragma unroll
    for (int t = 0; t < NF; t++) {
        int i4 = w * (D / 4) + lane + 32 * t;
        bf16 h0, l0, h1, l1, h2, l2, h3, l3;
        bsplit(acc[t].x, h0, l0); bsplit(acc[t].y, h1, l1);
        bsplit(acc[t].z, h2, l2); bsplit(acc[t].w, h3, l3);
        ((bf162*)oh)[i4 * 2 + 0] = bf162{h0, h1};
        ((bf162*)oh)[i4 * 2 + 1] = bf162{h2, h3};
        ((bf162*)ol)[i4 * 2 + 0] = bf162{l0, l1};
        ((bf162*)ol)[i4 * 2 + 1] = bf162{l2, l3};
    }
}

// ---------------- bf16x2 tensor-core GEMM -----------------------------------
// C[M x 256] = (Ah+Al)[M x K] @ (Bh+Bl)^T   (B planes are [N][K])
// block 128(M) x 256(N full), BK=16, 256 threads = 8 warps, warp tile 64x64.
#define SK 24                      // smem row stride (bf16); conflict-free frag loads
#define STG 18432                  // bf16 per stage: A 2*3072 + B 2*6144
#define TGB_SMEM (size_t)(2 * STG * sizeof(bf16))  // 73728 B

template <int K, bool GELU, bool STATS, bool PLANES>
__global__ void __launch_bounds__(256, 1) k_bgemm(
        const bf16* __restrict__ Ah, const bf16* __restrict__ Al,
        const bf16* __restrict__ BhT, const bf16* __restrict__ BlT,
        const float* __restrict__ bias, float* __restrict__ C,
        bf16* __restrict__ Ch, bf16* __restrict__ Cl, int M) {
    const int BM = 128, BK = 16;
    extern __shared__ bf16 smp[];

    int bm = blockIdx.x * BM;
    int tid = threadIdx.x;
    int wid = tid >> 5, lane = tid & 31;
    int g = lane >> 2, t = lane & 3;
    int warp_m = (wid & 1) * 64;   // 0 or 64
    int warp_n = (wid >> 1) * 64;  // 0,64,128,192

    // global load mapping
    int arow = tid >> 1, ahalf = (tid & 1) * 8;  // A: 128 rows x 16
    int bno = tid;                                // B: 256 rows x 16
    const bf16* aptr_h = Ah + (size_t)(bm + arow) * K + ahalf;
    const bf16* aptr_l = Al + (size_t)(bm + arow) * K + ahalf;
    const bf16* bptr_h = BhT + (size_t)bno * K;
    const bf16* bptr_l = BlT + (size_t)bno * K;
    bool aok = (bm + arow) < M;
    uint4 zero4 = make_uint4(0, 0, 0, 0);

    float acc[4][8][4];
#pragma unroll
    for (int m = 0; m < 4; m++)
#pragma unroll
        for (int n = 0; n < 8; n++)
#pragma unroll
            for (int c = 0; c < 4; c++) acc[m][n][c] = 0.f;

    // stage 0 fill
    {
        uint4 vah = aok ? *(const uint4*)aptr_h : zero4;
        uint4 val = aok ? *(const uint4*)aptr_l : zero4;
        uint4 vbh0 = *(const uint4*)(bptr_h + 0);
        uint4 vbh8 = *(const uint4*)(bptr_h + 8);
        uint4 vbl0 = *(const uint4*)(bptr_l + 0);
        uint4 vbl8 = *(const uint4*)(bptr_l + 8);
        *(uint4*)&smp[arow * SK + ahalf] = vah;
        *(uint4*)&smp[3072 + arow * SK + ahalf] = val;
        *(uint4*)&smp[6144 + bno * SK + 0] = vbh0;
        *(uint4*)&smp[6144 + bno * SK + 8] = vbh8;
        *(uint4*)&smp[12288 + bno * SK + 0] = vbl0;
        *(uint4*)&smp[12288 + bno * SK + 8] = vbl8;
    }
    __syncthreads();

    int buf = 0;
#pragma unroll 2
    for (int k0 = BK; k0 <= K; k0 += BK) {
        bool more = k0 < K;
        uint4 pah, pal, pbh0, pbh8, pbl0, pbl8;
        if (more) {
            pah = aok ? *(const uint4*)(aptr_h + k0) : zero4;
            pal = aok ? *(const uint4*)(aptr_l + k0) : zero4;
            pbh0 = *(const uint4*)(bptr_h + k0 + 0);
            pbh8 = *(const uint4*)(bptr_h + k0 + 8);
            pbl0 = *(const uint4*)(bptr_l + k0 + 0);
            pbl8 = *(const uint4*)(bptr_l + k0 + 8);
        }

        const bf16* ash = smp + buf * STG;
        const bf16* asl = ash + 3072;
        const bf16* bsh = ash + 6144;
        const bf16* bsl = ash + 12288;

        unsigned aH[4][4], aL[4][4];
#pragma unroll
        for (int m = 0; m < 4; m++) {
            int r1 = (warp_m + m * 16 + g) * SK;
            aH[m][0] = *(const unsigned*)(ash + r1 + 2 * t);
            aH[m][1] = *(const unsigned*)(ash + r1 + 8 * SK + 2 * t);
            aH[m][2] = *(const unsigned*)(ash + r1 + 8 + 2 * t);
            aH[m][3] = *(const unsigned*)(ash + r1 + 8 * SK + 8 + 2 * t);
            aL[m][0] = *(const unsigned*)(asl + r1 + 2 * t);
            aL[m][1] = *(const unsigned*)(asl + r1 + 8 * SK + 2 * t);
            aL[m][2] = *(const unsigned*)(asl + r1 + 8 + 2 * t);
            aL[m][3] = *(const unsigned*)(asl + r1 + 8 * SK + 8 + 2 * t);
        }
#pragma unroll
        for (int n = 0; n < 8; n++) {
            int cb = (warp_n + n * 8 + g) * SK;
            unsigned bh0 = *(const unsigned*)(bsh + cb + 2 * t);
            unsigned bh1 = *(const unsigned*)(bsh + cb + 8 + 2 * t);
            unsigned bl0 = *(const unsigned*)(bsl + cb + 2 * t);
            unsigned bl1 = *(const unsigned*)(bsl + cb + 8 + 2 * t);
#pragma unroll
            for (int m = 0; m < 4; m++) {
                float* c = acc[m][n];
                mma_bf16(c[0], c[1], c[2], c[3],
                         aH[m][0], aH[m][1], aH[m][2], aH[m][3], bl0, bl1);
                mma_bf16(c[0], c[1], c[2], c[3],
                         aL[m][0], aL[m][1], aL[m][2], aL[m][3], bh0, bh1);
                mma_bf16(c[0], c[1], c[2], c[3],
                         aH[m][0], aH[m][1], aH[m][2], aH[m][3], bh0, bh1);
            }
        }

        if (more) {
            int nb = buf ^ 1;
            bf16* d = smp + nb * STG;
            *(uint4*)&d[arow * SK + ahalf] = pah;
            *(uint4*)&d[3072 + arow * SK + ahalf] = pal;
            *(uint4*)&d[6144 + bno * SK + 0] = pbh0;
            *(uint4*)&d[6144 + bno * SK + 8] = pbh8;
            *(uint4*)&d[12288 + bno * SK + 0] = pbl0;
            *(uint4*)&d[12288 + bno * SK + 8] = pbl8;
            __syncthreads();
            buf = nb;
        }
    }

    // ---- epilogue ----
    float s_sum[8][2], s_sq[8][2];
    if (STATS) {
#pragma unroll
        for (int n = 0; n < 8; n++)
#pragma unroll
            for (int p = 0; p < 2; p++) { s_sum[n][p] = 0.f; s_sq[n][p] = 0.f; }
    }
#pragma unroll
    for (int m = 0; m < 4; m++) {
        int row0 = bm + warp_m + m * 16;
#pragma unroll
        for (int n = 0; n < 8; n++) {
            int col = warp_n + n * 8 + t * 2;
            float b0 = __ldg(&bias[col]), b1 = __ldg(&bias[col + 1]);
#pragma unroll
            for (int half = 0; half < 2; half++) {
                int r = row0 + g + half * 8;
                if (r >= M) continue;
                float2 o = make_float2(acc[m][n][half * 2 + 0] + b0,
                                       acc[m][n][half * 2 + 1] + b1);
                if (STATS) {
                    s_sum[n][0] += o.x; s_sq[n][0] += o.x * o.x;
                    s_sum[n][1] += o.y; s_sq[n][1] += o.y * o.y;
                }
                if (GELU) { o.x = gelu_tanh(o.x); o.y = gelu_tanh(o.y); }
                if (PLANES) {
                    bf16 h0, l0, h1, l1;
                    bsplit(o.x, h0, l0); bsplit(o.y, h1, l1);
                    *(bf162*)(Ch + (size_t)r * DH + col) = bf162{h0, h1};
                    *(bf162*)(Cl + (size_t)r * DH + col) = bf162{l0, l1};
                } else {
                    *(float2*)(C + (size_t)r * DH + col) = o;
                }
            }
        }
    }
    if (STATS) {
#pragma unroll
        for (int n = 0; n < 8; n++)
#pragma unroll
            for (int p = 0; p < 2; p++) {
#pragma unroll
                for (int off = 4; off < 32; off <<= 1) {
                    s_sum[n][p] += __shfl_xor_sync(0xffffffffu, s_sum[n][p], off);
                    s_sq[n][p] += __shfl_xor_sync(0xffffffffu, s_sq[n][p], off);
                }
            }
        if (lane < 4) {
#pragma unroll
            for (int n = 0; n < 8; n++)
#pragma unroll
                for (int p = 0; p < 2; p++) {
                    int col = warp_n + n * 8 + lane * 2 + p;
                    atomicAdd(&g_stats[col], (double)s_sum[n][p]);
                    atomicAdd(&g_stats[DH + col], (double)s_sq[n][p]);
                }
        }
    }
}

// ---------------- batchnorm -------------------------------------------------
__global__ void k_zero_stats() {
    int i = blockIdx.x * blockDim.x + threadIdx.x;
    if (i < 2 * DH) g_stats[i] = 0.0;
}

__global__ void k_bn_final(const float* __restrict__ gamma, const float* __restrict__ beta) {
    int c = threadIdx.x;
    double mean = g_stats[c] / (double)NN;
    double var = g_stats[DH + c] / (double)NN - mean * mean;
    double sc = (double)gamma[c] / sqrt(var + 1e-5);
    g_scale[c] = (float)sc;
    g_shift[c] = (float)((double)beta[c] - mean * sc);
}

// MODE 0: fp32 out; MODE 1: bf16 planes out only
template <int MODE>
__global__ void k_bn_apply(const float* __restrict__ m, const float* __restrict__ res,
                           float* __restrict__ hout, bf16* __restrict__ oh,
                           bf16* __restrict__ ol) {
    int idx = blockIdx.x * blockDim.x + threadIdx.x;  // float4 index
    if (idx >= NN * (DH / 4)) return;
    int c4 = (idx & (DH / 4 - 1)) * 4;
    float4 v = ((const float4*)m)[idx];
    float4 r = ((const float4*)res)[idx];
    float4 o;
    o.x = gelu_tanh(v.x * g_scale[c4 + 0] + g_shift[c4 + 0]) + r.x;
    o.y = gelu_tanh(v.y * g_scale[c4 + 1] + g_shift[c4 + 1]) + r.y;
    o.z = gelu_tanh(v.z * g_scale[c4 + 2] + g_shift[c4 + 2]) + r.z;
    o.w = gelu_tanh(v.w * g_scale[c4 + 3] + g_shift[c4 + 3]) + r.w;
    if (MODE == 0) {
        ((float4*)hout)[idx] = o;
    } else {
        bf16 h0, l0, h1, l1, h2, l2, h3, l3;
        bsplit(o.x, h0, l0); bsplit(o.y, h1, l1);
        bsplit(o.z, h2, l2); bsplit(o.w, h3, l3);
        ((bf162*)oh)[idx * 2 + 0] = bf162{h0, h1};
        ((bf162*)oh)[idx * 2 + 1] = bf162{h2, h3};
        ((bf162*)ol)[idx * 2 + 0] = bf162{l0, l1};
        ((bf162*)ol)[idx * 2 + 1] = bf162{l2, l3};
    }
}

// ---------------- head ------------------------------------------------------
__global__ void k_head(const float* __restrict__ h, const float* __restrict__ w,
                       const float* __restrict__ b, const int* __restrict__ mask,
                       float* __restrict__ out) {
    int gw = (blockIdx.x * blockDim.x + threadIdx.x) >> 5;
    int lane = threadIdx.x & 31;
    if (gw >= NN) return;
    const float4* row = (const float4*)(h + (size_t)gw * DH);
    const float4* w4 = (const float4*)w;
    float s = 0.f;
#pragma unroll
    for (int t = 0; t < 2; t++) {
        int j = lane + t * 32;
        float4 a = row[j];
        float4 ww = __ldg(&w4[j]);
        s += a.x * ww.x + a.y * ww.y + a.z * ww.z + a.w * ww.w;
    }
#pragma unroll
    for (int o = 16; o; o >>= 1) s += __shfl_xor_sync(0xffffffffu, s, o);
    if (lane == 0) out[gw] = (mask[gw] != 0) ? (s + __ldg(&b[0])) : 0.0f;
}

// ---------------- launch -----------------------------------------------------
extern "C" void kernel_launch(void* const* d_in, const int* in_sizes, int n_in,
                              void* d_out, int out_size) {
    const float* x = (const float*)d_in[0];
    const int* ei = (const int*)d_in[1];
    const int* mask = (const int*)d_in[2];
    const float* conv_w0 = (const float*)d_in[3];
    const float* conv_b0 = (const float*)d_in[4];
    const float* conv_w1 = (const float*)d_in[5];
    const float* conv_b1 = (const float*)d_in[6];
    const float* conv_w2 = (const float*)d_in[7];
    const float* conv_b2 = (const float*)d_in[8];
    const float* bn_g0 = (const float*)d_in[9];
    const float* bn_b0 = (const float*)d_in[10];
    const float* bn_g1 = (const float*)d_in[11];
    const float* bn_b1 = (const float*)d_in[12];
    const float* bn_g2 = (const float*)d_in[13];
    const float* bn_b2 = (const float*)d_in[14];
    const float* proj_w = (const float*)d_in[15];
    const float* proj_b = (const float*)d_in[16];
    const float* lin_w0 = (const float*)d_in[17];
    const float* lin_b0 = (const float*)d_in[18];
    const float* lin_w1 = (const float*)d_in[19];
    const float* lin_b1 = (const float*)d_in[20];
    const float* head_w = (const float*)d_in[21];
    const float* head_b = (const float*)d_in[22];
    float* out = (float*)d_out;

    const int* src = ei;
    const int* dst = ei + EE;

    float *p_h, *p_m, *p_res;
    bf16 *p1h, *p1l, *p2h, *p2l, *wh, *wl;
    cudaGetSymbolAddress((void**)&p_h, g_h);
    cudaGetSymbolAddress((void**)&p_m, g_m);
    cudaGetSymbolAddress((void**)&p_res, g_res);
    cudaGetSymbolAddress((void**)&p1h, g_p1h);
    cudaGetSymbolAddress((void**)&p1l, g_p1l);
    cudaGetSymbolAddress((void**)&p2h, g_p2h);
    cudaGetSymbolAddress((void**)&p2l, g_p2l);
    cudaGetSymbolAddress((void**)&wh, g_wh);
    cudaGetSymbolAddress((void**)&wl, g_wl);

    cudaFuncSetAttribute(k_bgemm<DIN, false, false, false>, cudaFuncAttributeMaxDynamicSharedMemorySize, (int)TGB_SMEM);
    cudaFuncSetAttribute(k_bgemm<DIN, false, true, false>, cudaFuncAttributeMaxDynamicSharedMemorySize, (int)TGB_SMEM);
    cudaFuncSetAttribute(k_bgemm<DH, false, true, false>, cudaFuncAttributeMaxDynamicSharedMemorySize, (int)TGB_SMEM);
    cudaFuncSetAttribute(k_bgemm<DH, true, false, true>, cudaFuncAttributeMaxDynamicSharedMemorySize, (int)TGB_SMEM);
    cudaFuncSetAttribute(k_bgemm<DH, true, false, false>, cudaFuncAttributeMaxDynamicSharedMemorySize, (int)TGB_SMEM);

    const int T = 256;
    const int WSTRIDE = DH * DH;
    dim3 tg_grid((NN + 127) / 128);  // 391, full-width N
    int ew4_256 = NN * (DH / 4);
    int gather_blocks = (NN * 32 + T - 1) / T;

    // launches 1-3: split x + proj weight, zero counts
    k_zero_cnt<<<(NN + T - 1) / T, T>>>();
    k_split_x<<<(NN * DIN / 4 + T - 1) / T, T>>>(x, p1h, p1l);
    k_split_w<<<(DIN * DH + T - 1) / T, T>>>(proj_w, DIN, wh + 0 * WSTRIDE, wl + 0 * WSTRIDE);

    // launch 4 (profiled): residual projection res = x @ proj_w + proj_b
    k_bgemm<DIN, false, false, false><<<tg_grid, T, TGB_SMEM>>>(
        p1h, p1l, wh + 0 * WSTRIDE, wl + 0 * WSTRIDE, proj_b, p_res, nullptr, nullptr, NN);

    // ---- degrees + remaining splits ----
    k_deg_count<<<(EE + T - 1) / T, T>>>(dst);
    k_deg_final<<<(NN + T - 1) / T, T>>>();
    k_split_w<<<(DIN * DH + T - 1) / T, T>>>(conv_w0, DIN, wh + 1 * WSTRIDE, wl + 1 * WSTRIDE);
    k_split_w<<<(DH * DH + T - 1) / T, T>>>(conv_w1, DH, wh + 2 * WSTRIDE, wl + 2 * WSTRIDE);
    k_split_w<<<(DH * DH + T - 1) / T, T>>>(conv_w2, DH, wh + 3 * WSTRIDE, wl + 3 * WSTRIDE);
    k_split_w<<<(DH * DH + T - 1) / T, T>>>(lin_w0, DH, wh + 4 * WSTRIDE, wl + 4 * WSTRIDE);
    k_split_w<<<(DH * DH + T - 1) / T, T>>>(lin_w1, DH, wh + 5 * WSTRIDE, wl + 5 * WSTRIDE);

    // ---- CSR build ----
    k_scan1<<<SCAN_B, 1024>>>();
    k_scan2<<<1, 64>>>();
    k_scan3<<<SCAN_B, 1024>>>();
    k_csr_fill<<<(EE + T - 1) / T, T>>>(src, dst);

    // ---- GCN layer 0 ----
    k_zero_stats<<<2, T>>>();
    k_gather<DIN><<<gather_blocks, T>>>(x, p2h, p2l);
    k_bgemm<DIN, false, true, false><<<tg_grid, T, TGB_SMEM>>>(
        p2h, p2l, wh + 1 * WSTRIDE, wl + 1 * WSTRIDE, conv_b0, p_m, nullptr, nullptr, NN);
    k_bn_final<<<1, T>>>(bn_g0, bn_b0);
    k_bn_apply<0><<<(ew4_256 + T - 1) / T, T>>>(p_m, p_res, p_h, nullptr, nullptr);

    // ---- GCN layer 1 ----
    k_zero_stats<<<2, T>>>();
    k_gather<DH><<<gather_blocks, T>>>(p_h, p2h, p2l);
    k_bgemm<DH, false, true, false><<<tg_grid, T, TGB_SMEM>>>(
        p2h, p2l, wh + 2 * WSTRIDE, wl + 2 * WSTRIDE, conv_b1, p_m, nullptr, nullptr, NN);
    k_bn_final<<<1, T>>>(bn_g1, bn_b1);
    k_bn_apply<0><<<(ew4_256 + T - 1) / T, T>>>(p_m, p_h, p_h, nullptr, nullptr);

    // ---- GCN layer 2 ----
    k_zero_stats<<<2, T>>>();
    k_gather<DH><<<gather_blocks, T>>>(p_h, p2h, p2l);
    k_bgemm<DH, false, true, false><<<tg_grid, T, TGB_SMEM>>>(
        p2h, p2l, wh + 3 * WSTRIDE, wl + 3 * WSTRIDE, conv_b2, p_m, nullptr, nullptr, NN);
    k_bn_final<<<1, T>>>(bn_g2, bn_b2);
    k_bn_apply<1><<<(ew4_256 + T - 1) / T, T>>>(p_m, p_h, nullptr, p1h, p1l);

    // ---- MLP ----
    k_bgemm<DH, true, false, true><<<tg_grid, T, TGB_SMEM>>>(
        p1h, p1l, wh + 4 * WSTRIDE, wl + 4 * WSTRIDE, lin_b0, nullptr, p2h, p2l, NN);
    k_bgemm<DH, true, false, false><<<tg_grid, T, TGB_SMEM>>>(
        p2h, p2l, wh + 5 * WSTRIDE, wl + 5 * WSTRIDE, lin_b1, p_h, nullptr, nullptr, NN);

    // ---- head ----
    k_head<<<(NN * 32 + T - 1) / T, T>>>(p_h, head_w, head_b, mask, out);
}